// round 2
// baseline (speedup 1.0000x reference)
#include <cuda_runtime.h>
#include <math.h>

#define L 2048
#define DM 1024
#define NH 16
#define HD 64

// Scratch (device globals — no allocation allowed)
__device__ __align__(16) float g_Q[L * DM];
__device__ __align__(16) float g_K[L * DM];
__device__ __align__(16) float g_V[L * DM];
__device__ __align__(16) float g_Y[L * DM];
__device__ __align__(16) float g_Vsuf[64 * DM];          // suffix sums of V at 32-row granularity
__device__ __align__(16) float g_A[(size_t)NH * L * L];  // head-softmaxed attention weights (lower triangle tiles only)

// -log2(500)/64
#define ROPE_LOG2C 0.14009037944784838

// ---------------------------------------------------------------------------
// Generic 2048x1024 @ 1024x1024 fp32 GEMM, optional fused RoPE epilogue.
// BM=64, BN=64, BK=16, 256 threads, 4x4 microtile.
// ---------------------------------------------------------------------------
__global__ __launch_bounds__(256) void gemm64(const float* __restrict__ A,
                                              const float* __restrict__ B,
                                              float* __restrict__ C,
                                              int doRope) {
    __shared__ float As[16][65];   // transposed A tile, padded
    __shared__ float Bs[16][68];   // B tile, padded (68 floats keeps 16B alignment)

    const int tid = threadIdx.x;
    const int m0 = blockIdx.y * 64;
    const int n0 = blockIdx.x * 64;
    const int ty = tid >> 4, tx = tid & 15;

    const int lr = tid >> 2, lc4 = tid & 3;    // A loader: row 0..63, f4-col 0..3
    const int br = tid >> 4, bc4 = tid & 15;   // B loader: row 0..15, f4-col 0..15

    float acc[4][4] = {};

    for (int k0 = 0; k0 < 1024; k0 += 16) {
        float4 av = *(const float4*)(A + (size_t)(m0 + lr) * 1024 + k0 + lc4 * 4);
        float4 bv = *(const float4*)(B + (size_t)(k0 + br) * 1024 + n0 + bc4 * 4);
        __syncthreads();
        As[lc4 * 4 + 0][lr] = av.x;
        As[lc4 * 4 + 1][lr] = av.y;
        As[lc4 * 4 + 2][lr] = av.z;
        As[lc4 * 4 + 3][lr] = av.w;
        *(float4*)(&Bs[br][bc4 * 4]) = bv;
        __syncthreads();
#pragma unroll
        for (int kk = 0; kk < 16; kk++) {
            float a[4];
#pragma unroll
            for (int i = 0; i < 4; i++) a[i] = As[kk][ty * 4 + i];
            float4 b = *(const float4*)(&Bs[kk][tx * 4]);
#pragma unroll
            for (int i = 0; i < 4; i++) {
                acc[i][0] += a[i] * b.x;
                acc[i][1] += a[i] * b.y;
                acc[i][2] += a[i] * b.z;
                acc[i][3] += a[i] * b.w;
            }
        }
    }

#pragma unroll
    for (int i = 0; i < 4; i++) {
        int m = m0 + ty * 4 + i;
        float o0 = acc[i][0], o1 = acc[i][1], o2 = acc[i][2], o3 = acc[i][3];
        if (doRope) {
            int nb = n0 + tx * 4;  // even, pairs (0,1),(2,3) inside this thread
            {
                int t = nb & 63;
                float fr = (float)exp2(-(double)t * ROPE_LOG2C);
                float th = (float)m * fr;
                float s, c;
                sincosf(th, &s, &c);
                float xe = o0, xo = o1;
                o0 = xe * c - xo * s;
                o1 = xe * s + xo * c;
            }
            {
                int t = (nb + 2) & 63;
                float fr = (float)exp2(-(double)t * ROPE_LOG2C);
                float th = (float)m * fr;
                float s, c;
                sincosf(th, &s, &c);
                float xe = o2, xo = o3;
                o2 = xe * c - xo * s;
                o3 = xe * s + xo * c;
            }
        }
        *(float4*)(C + (size_t)m * 1024 + n0 + tx * 4) = make_float4(o0, o1, o2, o3);
    }
}

// ---------------------------------------------------------------------------
// Suffix sums of V: g_Vsuf[j][c] = sum_{k >= 32*j} V[k][c]
// ---------------------------------------------------------------------------
__global__ __launch_bounds__(256) void v_suffix() {
    int c = blockIdx.x * 256 + threadIdx.x;  // 0..1023
    float run = 0.f;
    for (int k = L - 1; k >= 0; k--) {
        run += g_V[(size_t)k * DM + c];
        if ((k & 31) == 0) g_Vsuf[(size_t)(k >> 5) * DM + c] = run;
    }
}

// ---------------------------------------------------------------------------
// Scores + head-axis softmax.
// Tile: 64 queries x 32 keys. All 16 heads' scores staged in smem, then
// softmax across h per (q,k) cell. Only lower-triangle tiles (k0 < q0+64)
// are computed/written; fully-masked tiles are never touched (AV uses the
// V suffix sum for them).
// Dynamic smem: S[16][64][33] + Qs[64][68] + Ks[32][68] = 161280 bytes.
// ---------------------------------------------------------------------------
__global__ __launch_bounds__(256) void attn_scores() {
    extern __shared__ float sm[];
    float* S = sm;                  // 16*64*33 = 33792 floats
    float* Qs = sm + 16 * 64 * 33;  // 64*68
    float* Ks = Qs + 64 * 68;       // 32*68

    const int k0 = blockIdx.x * 32;
    const int q0 = blockIdx.y * 64;
    if (k0 >= q0 + 64) return;  // fully masked tile: handled via V suffix in AV

    const int tid = threadIdx.x;
    const int tq = tid >> 3, tk = tid & 7;
    const int qiA = tq * 2, kj0 = tk * 4;  // thread owns 2 q-rows x 4 k-cols

    for (int h = 0; h < NH; h++) {
        __syncthreads();
#pragma unroll
        for (int it = 0; it < 4; it++) {
            int idx = tid + it * 256;
            int row = idx >> 4, c4 = idx & 15;
            *(float4*)(Qs + row * 68 + c4 * 4) =
                *(const float4*)(g_Q + (size_t)(q0 + row) * DM + h * HD + c4 * 4);
        }
#pragma unroll
        for (int it = 0; it < 2; it++) {
            int idx = tid + it * 256;
            int row = idx >> 4, c4 = idx & 15;
            *(float4*)(Ks + row * 68 + c4 * 4) =
                *(const float4*)(g_K + (size_t)(k0 + row) * DM + h * HD + c4 * 4);
        }
        __syncthreads();

        float acc[2][4] = {};
#pragma unroll
        for (int c4 = 0; c4 < 16; c4++) {
            float4 qa = *(const float4*)(Qs + qiA * 68 + c4 * 4);
            float4 qb = *(const float4*)(Qs + (qiA + 1) * 68 + c4 * 4);
#pragma unroll
            for (int j = 0; j < 4; j++) {
                float4 kv = *(const float4*)(Ks + (kj0 + j) * 68 + c4 * 4);
                acc[0][j] += qa.x * kv.x + qa.y * kv.y + qa.z * kv.z + qa.w * kv.w;
                acc[1][j] += qb.x * kv.x + qb.y * kv.y + qb.z * kv.z + qb.w * kv.w;
            }
        }
        float* Sh = S + h * (64 * 33);
#pragma unroll
        for (int i = 0; i < 2; i++)
#pragma unroll
            for (int j = 0; j < 4; j++)
                Sh[(qiA + i) * 33 + kj0 + j] = acc[i][j] * 0.125f;  // 1/sqrt(64)
    }
    __syncthreads();

    // Softmax across the 16 heads, per (q,k) cell (each thread owns its cells)
#pragma unroll
    for (int i = 0; i < 2; i++) {
        int qi = qiA + i, q = q0 + qi;
#pragma unroll
        for (int j = 0; j < 4; j++) {
            int kj = kj0 + j, k = k0 + kj;
            float* cell = S + qi * 33 + kj;
            if (k > q) {
#pragma unroll
                for (int h = 0; h < NH; h++) cell[h * (64 * 33)] = 0.0625f;  // 1/16
            } else {
                float mx = -1e30f;
#pragma unroll
                for (int h = 0; h < NH; h++) mx = fmaxf(mx, cell[h * (64 * 33)]);
                float e[NH];
                float sum = 0.f;
#pragma unroll
                for (int h = 0; h < NH; h++) {
                    e[h] = __expf(cell[h * (64 * 33)] - mx);
                    sum += e[h];
                }
                float inv = 1.0f / sum;
#pragma unroll
                for (int h = 0; h < NH; h++) cell[h * (64 * 33)] = e[h] * inv;
            }
        }
    }
    __syncthreads();

    // Coalesced writeback of A
    for (int idx = tid; idx < NH * 64 * 32; idx += 256) {
        int h = idx >> 11;
        int rem = idx & 2047;
        int qi = rem >> 5, kj = rem & 31;
        g_A[((size_t)h << 22) + (size_t)(q0 + qi) * L + (k0 + kj)] =
            S[h * (64 * 33) + qi * 33 + kj];
    }
}

// ---------------------------------------------------------------------------
// Y[q, h*64+j] = sum_{k<klim} A[h,q,k] V[k, h*64+j] + (1/16)*Vsuf[klim..][h*64+j]
// Per (q-tile of 64, head): GEMM 64 x 64 x klim, BK=32.
// ---------------------------------------------------------------------------
__global__ __launch_bounds__(256) void attn_av() {
    __shared__ float As[32][65];
    __shared__ float Bs[32][68];

    const int q0 = blockIdx.x * 64;
    const int h = blockIdx.y;
    const int tid = threadIdx.x;
    const int ty = tid >> 4, tx = tid & 15;
    const int klim = (q0 + 64 < L) ? (q0 + 64) : L;

    const float* Abase = g_A + ((size_t)h << 22);
    float acc[4][4] = {};

    for (int k0 = 0; k0 < klim; k0 += 32) {
        __syncthreads();
#pragma unroll
        for (int it = 0; it < 2; it++) {
            int idx = tid + it * 256;
            int r = idx >> 3, c4 = idx & 7;
            float4 av = *(const float4*)(Abase + (size_t)(q0 + r) * L + k0 + c4 * 4);
            As[c4 * 4 + 0][r] = av.x;
            As[c4 * 4 + 1][r] = av.y;
            As[c4 * 4 + 2][r] = av.z;
            As[c4 * 4 + 3][r] = av.w;
        }
#pragma unroll
        for (int it = 0; it < 2; it++) {
            int idx = tid + it * 256;
            int r = idx >> 4, c4 = idx & 15;
            *(float4*)(&Bs[r][c4 * 4]) =
                *(const float4*)(g_V + (size_t)(k0 + r) * DM + h * HD + c4 * 4);
        }
        __syncthreads();
#pragma unroll
        for (int kk = 0; kk < 32; kk++) {
            float a[4];
#pragma unroll
            for (int i = 0; i < 4; i++) a[i] = As[kk][ty * 4 + i];
            float4 b = *(const float4*)(&Bs[kk][tx * 4]);
#pragma unroll
            for (int i = 0; i < 4; i++) {
                acc[i][0] += a[i] * b.x;
                acc[i][1] += a[i] * b.y;
                acc[i][2] += a[i] * b.z;
                acc[i][3] += a[i] * b.w;
            }
        }
    }

    // Masked tail: uniform 1/16 weights times the V suffix sum
    float4 sufv = make_float4(0.f, 0.f, 0.f, 0.f);
    if (klim < L) {
        float4 v = *(const float4*)(g_Vsuf + (size_t)(klim >> 5) * DM + h * HD + tx * 4);
        sufv = make_float4(0.0625f * v.x, 0.0625f * v.y, 0.0625f * v.z, 0.0625f * v.w);
    }
#pragma unroll
    for (int i = 0; i < 4; i++) {
        int m = q0 + ty * 4 + i;
        *(float4*)(g_Y + (size_t)m * DM + h * HD + tx * 4) =
            make_float4(acc[i][0] + sufv.x, acc[i][1] + sufv.y,
                        acc[i][2] + sufv.z, acc[i][3] + sufv.w);
    }
}

// ---------------------------------------------------------------------------
extern "C" void kernel_launch(void* const* d_in, const int* in_sizes, int n_in,
                              void* d_out, int out_size) {
    const float* X = (const float*)d_in[0];
    // d_in[1] = mask (int32 tril) — structure known, handled analytically
    const float* Wq = (const float*)d_in[2];
    const float* Wk = (const float*)d_in[3];
    const float* Wv = (const float*)d_in[4];
    const float* Wo = (const float*)d_in[5];
    float* Out = (float*)d_out;

    float *Qp, *Kp, *Vp, *Yp;
    cudaGetSymbolAddress((void**)&Qp, g_Q);
    cudaGetSymbolAddress((void**)&Kp, g_K);
    cudaGetSymbolAddress((void**)&Vp, g_V);
    cudaGetSymbolAddress((void**)&Yp, g_Y);

    const int SMEM_SC = (16 * 64 * 33 + 64 * 68 + 32 * 68) * 4;  // 161280 B
    cudaFuncSetAttribute(attn_scores, cudaFuncAttributeMaxDynamicSharedMemorySize, SMEM_SC);

    dim3 gProj(1024 / 64, 2048 / 64);  // (16, 32)
    gemm64<<<gProj, 256>>>(X, Wq, Qp, 1);
    gemm64<<<gProj, 256>>>(X, Wk, Kp, 1);
    gemm64<<<gProj, 256>>>(X, Wv, Vp, 0);

    v_suffix<<<4, 256>>>();

    attn_scores<<<dim3(L / 32, L / 64), 256, SMEM_SC>>>();

    attn_av<<<dim3(L / 64, NH), 256>>>();

    gemm64<<<gProj, 256>>>(Yp, Wo, Out, 0);
}

// round 3
// speedup vs baseline: 1.2843x; 1.2843x over previous
#include <cuda_runtime.h>
#include <math.h>

#define L 2048
#define DM 1024
#define NH 16
#define HD 64

// Scratch (device globals — no allocation allowed)
__device__ __align__(16) float g_Q[L * DM];
__device__ __align__(16) float g_K[L * DM];
__device__ __align__(16) float g_V[L * DM];
__device__ __align__(16) float g_Y[L * DM];
__device__ __align__(16) float g_part[64 * DM];          // per-32-row-chunk column sums of V
__device__ __align__(16) float g_Vsuf[64 * DM];          // suffix sums of V at 32-row granularity
__device__ __align__(16) float g_A[(size_t)NH * L * L];  // head-softmaxed attention weights (lower triangle tiles only)

// -log2(500)/64
#define ROPE_LOG2C 0.14009037944784838

// ---------------------------------------------------------------------------
// Generic 2048x1024 @ 1024x1024 fp32 GEMM, optional fused RoPE epilogue.
// BM=64, BN=64, BK=16, 256 threads, 4x4 microtile.
// ---------------------------------------------------------------------------
__global__ __launch_bounds__(256) void gemm64(const float* __restrict__ A,
                                              const float* __restrict__ B,
                                              float* __restrict__ C,
                                              int doRope) {
    __shared__ float As[16][65];   // transposed A tile, padded
    __shared__ float Bs[16][68];   // B tile, padded (68 floats keeps 16B alignment)

    const int tid = threadIdx.x;
    const int m0 = blockIdx.y * 64;
    const int n0 = blockIdx.x * 64;
    const int ty = tid >> 4, tx = tid & 15;

    const int lr = tid >> 2, lc4 = tid & 3;    // A loader: row 0..63, f4-col 0..3
    const int br = tid >> 4, bc4 = tid & 15;   // B loader: row 0..15, f4-col 0..15

    float acc[4][4] = {};

    for (int k0 = 0; k0 < 1024; k0 += 16) {
        float4 av = *(const float4*)(A + (size_t)(m0 + lr) * 1024 + k0 + lc4 * 4);
        float4 bv = *(const float4*)(B + (size_t)(k0 + br) * 1024 + n0 + bc4 * 4);
        __syncthreads();
        As[lc4 * 4 + 0][lr] = av.x;
        As[lc4 * 4 + 1][lr] = av.y;
        As[lc4 * 4 + 2][lr] = av.z;
        As[lc4 * 4 + 3][lr] = av.w;
        *(float4*)(&Bs[br][bc4 * 4]) = bv;
        __syncthreads();
#pragma unroll
        for (int kk = 0; kk < 16; kk++) {
            float a[4];
#pragma unroll
            for (int i = 0; i < 4; i++) a[i] = As[kk][ty * 4 + i];
            float4 b = *(const float4*)(&Bs[kk][tx * 4]);
#pragma unroll
            for (int i = 0; i < 4; i++) {
                acc[i][0] += a[i] * b.x;
                acc[i][1] += a[i] * b.y;
                acc[i][2] += a[i] * b.z;
                acc[i][3] += a[i] * b.w;
            }
        }
    }

#pragma unroll
    for (int i = 0; i < 4; i++) {
        int m = m0 + ty * 4 + i;
        float o0 = acc[i][0], o1 = acc[i][1], o2 = acc[i][2], o3 = acc[i][3];
        if (doRope) {
            int nb = n0 + tx * 4;  // even, pairs (0,1),(2,3) inside this thread
            {
                int t = nb & 63;
                float fr = (float)exp2(-(double)t * ROPE_LOG2C);
                float th = (float)m * fr;
                float s, c;
                sincosf(th, &s, &c);
                float xe = o0, xo = o1;
                o0 = xe * c - xo * s;
                o1 = xe * s + xo * c;
            }
            {
                int t = (nb + 2) & 63;
                float fr = (float)exp2(-(double)t * ROPE_LOG2C);
                float th = (float)m * fr;
                float s, c;
                sincosf(th, &s, &c);
                float xe = o2, xo = o3;
                o2 = xe * c - xo * s;
                o3 = xe * s + xo * c;
            }
        }
        *(float4*)(C + (size_t)m * 1024 + n0 + tx * 4) = make_float4(o0, o1, o2, o3);
    }
}

// ---------------------------------------------------------------------------
// Phase 1: per-chunk column partial sums. g_part[j][c] = sum_{k in chunk j} V[k][c]
// grid (64 chunks, 4 column groups) x 256 threads — full-chip parallel.
// ---------------------------------------------------------------------------
__global__ __launch_bounds__(256) void v_partial() {
    int j = blockIdx.x;                               // chunk 0..63
    int c = blockIdx.y * 256 + threadIdx.x;           // column 0..1023
    const float* base = g_V + (size_t)(j * 32) * DM + c;
    float s = 0.f;
#pragma unroll
    for (int r = 0; r < 32; r++) s += base[(size_t)r * DM];
    g_part[(size_t)j * DM + c] = s;
}

// ---------------------------------------------------------------------------
// Phase 2: suffix over chunk partials. g_Vsuf[j][c] = sum_{i >= j} g_part[i][c]
// Each thread computes one (j, c) independently — no sequential depth across
// threads; g_part (256 KB) is L2-resident.
// ---------------------------------------------------------------------------
__global__ __launch_bounds__(256) void v_suffix2() {
    int j = blockIdx.x;                               // 0..63
    int c = blockIdx.y * 256 + threadIdx.x;           // 0..1023
    float s = 0.f;
    for (int i = j; i < 64; i++) s += g_part[(size_t)i * DM + c];
    g_Vsuf[(size_t)j * DM + c] = s;
}

// ---------------------------------------------------------------------------
// Scores + head-axis softmax.
// Tile: 64 queries x 32 keys. All 16 heads' scores staged in smem, then
// softmax across h per (q,k) cell. Only lower-triangle tiles (k0 < q0+64)
// are computed/written; fully-masked tiles are never touched (AV uses the
// V suffix sum for them).
// Dynamic smem: S[16][64][33] + Qs[64][68] + Ks[32][68] = 161280 bytes.
// ---------------------------------------------------------------------------
__global__ __launch_bounds__(256) void attn_scores() {
    extern __shared__ float sm[];
    float* S = sm;                  // 16*64*33 = 33792 floats
    float* Qs = sm + 16 * 64 * 33;  // 64*68
    float* Ks = Qs + 64 * 68;       // 32*68

    const int k0 = blockIdx.x * 32;
    const int q0 = blockIdx.y * 64;
    if (k0 >= q0 + 64) return;  // fully masked tile: handled via V suffix in AV

    const int tid = threadIdx.x;
    const int tq = tid >> 3, tk = tid & 7;
    const int qiA = tq * 2, kj0 = tk * 4;  // thread owns 2 q-rows x 4 k-cols

    for (int h = 0; h < NH; h++) {
        __syncthreads();
#pragma unroll
        for (int it = 0; it < 4; it++) {
            int idx = tid + it * 256;
            int row = idx >> 4, c4 = idx & 15;
            *(float4*)(Qs + row * 68 + c4 * 4) =
                *(const float4*)(g_Q + (size_t)(q0 + row) * DM + h * HD + c4 * 4);
        }
#pragma unroll
        for (int it = 0; it < 2; it++) {
            int idx = tid + it * 256;
            int row = idx >> 4, c4 = idx & 15;
            *(float4*)(Ks + row * 68 + c4 * 4) =
                *(const float4*)(g_K + (size_t)(k0 + row) * DM + h * HD + c4 * 4);
        }
        __syncthreads();

        float acc[2][4] = {};
#pragma unroll
        for (int c4 = 0; c4 < 16; c4++) {
            float4 qa = *(const float4*)(Qs + qiA * 68 + c4 * 4);
            float4 qb = *(const float4*)(Qs + (qiA + 1) * 68 + c4 * 4);
#pragma unroll
            for (int j = 0; j < 4; j++) {
                float4 kv = *(const float4*)(Ks + (kj0 + j) * 68 + c4 * 4);
                acc[0][j] += qa.x * kv.x + qa.y * kv.y + qa.z * kv.z + qa.w * kv.w;
                acc[1][j] += qb.x * kv.x + qb.y * kv.y + qb.z * kv.z + qb.w * kv.w;
            }
        }
        float* Sh = S + h * (64 * 33);
#pragma unroll
        for (int i = 0; i < 2; i++)
#pragma unroll
            for (int j = 0; j < 4; j++)
                Sh[(qiA + i) * 33 + kj0 + j] = acc[i][j] * 0.125f;  // 1/sqrt(64)
    }
    __syncthreads();

    // Softmax across the 16 heads, per (q,k) cell (each thread owns its cells)
#pragma unroll
    for (int i = 0; i < 2; i++) {
        int qi = qiA + i, q = q0 + qi;
#pragma unroll
        for (int j = 0; j < 4; j++) {
            int kj = kj0 + j, k = k0 + kj;
            float* cell = S + qi * 33 + kj;
            if (k > q) {
#pragma unroll
                for (int h = 0; h < NH; h++) cell[h * (64 * 33)] = 0.0625f;  // 1/16
            } else {
                float mx = -1e30f;
#pragma unroll
                for (int h = 0; h < NH; h++) mx = fmaxf(mx, cell[h * (64 * 33)]);
                float e[NH];
                float sum = 0.f;
#pragma unroll
                for (int h = 0; h < NH; h++) {
                    e[h] = __expf(cell[h * (64 * 33)] - mx);
                    sum += e[h];
                }
                float inv = 1.0f / sum;
#pragma unroll
                for (int h = 0; h < NH; h++) cell[h * (64 * 33)] = e[h] * inv;
            }
        }
    }
    __syncthreads();

    // Coalesced writeback of A
    for (int idx = tid; idx < NH * 64 * 32; idx += 256) {
        int h = idx >> 11;
        int rem = idx & 2047;
        int qi = rem >> 5, kj = rem & 31;
        g_A[((size_t)h << 22) + (size_t)(q0 + qi) * L + (k0 + kj)] =
            S[h * (64 * 33) + qi * 33 + kj];
    }
}

// ---------------------------------------------------------------------------
// Y[q, h*64+j] = sum_{k<klim} A[h,q,k] V[k, h*64+j] + (1/16)*Vsuf[klim..][h*64+j]
// Per (q-tile of 64, head): GEMM 64 x 64 x klim, BK=32.
// ---------------------------------------------------------------------------
__global__ __launch_bounds__(256) void attn_av() {
    __shared__ float As[32][65];
    __shared__ float Bs[32][68];

    const int q0 = blockIdx.x * 64;
    const int h = blockIdx.y;
    const int tid = threadIdx.x;
    const int ty = tid >> 4, tx = tid & 15;
    const int klim = (q0 + 64 < L) ? (q0 + 64) : L;

    const float* Abase = g_A + ((size_t)h << 22);
    float acc[4][4] = {};

    for (int k0 = 0; k0 < klim; k0 += 32) {
        __syncthreads();
#pragma unroll
        for (int it = 0; it < 2; it++) {
            int idx = tid + it * 256;
            int r = idx >> 3, c4 = idx & 7;
            float4 av = *(const float4*)(Abase + (size_t)(q0 + r) * L + k0 + c4 * 4);
            As[c4 * 4 + 0][r] = av.x;
            As[c4 * 4 + 1][r] = av.y;
            As[c4 * 4 + 2][r] = av.z;
            As[c4 * 4 + 3][r] = av.w;
        }
#pragma unroll
        for (int it = 0; it < 2; it++) {
            int idx = tid + it * 256;
            int r = idx >> 4, c4 = idx & 15;
            *(float4*)(&Bs[r][c4 * 4]) =
                *(const float4*)(g_V + (size_t)(k0 + r) * DM + h * HD + c4 * 4);
        }
        __syncthreads();
#pragma unroll
        for (int kk = 0; kk < 32; kk++) {
            float a[4];
#pragma unroll
            for (int i = 0; i < 4; i++) a[i] = As[kk][ty * 4 + i];
            float4 b = *(const float4*)(&Bs[kk][tx * 4]);
#pragma unroll
            for (int i = 0; i < 4; i++) {
                acc[i][0] += a[i] * b.x;
                acc[i][1] += a[i] * b.y;
                acc[i][2] += a[i] * b.z;
                acc[i][3] += a[i] * b.w;
            }
        }
    }

    // Masked tail: uniform 1/16 weights times the V suffix sum
    float4 sufv = make_float4(0.f, 0.f, 0.f, 0.f);
    if (klim < L) {
        float4 v = *(const float4*)(g_Vsuf + (size_t)(klim >> 5) * DM + h * HD + tx * 4);
        sufv = make_float4(0.0625f * v.x, 0.0625f * v.y, 0.0625f * v.z, 0.0625f * v.w);
    }
#pragma unroll
    for (int i = 0; i < 4; i++) {
        int m = q0 + ty * 4 + i;
        *(float4*)(g_Y + (size_t)m * DM + h * HD + tx * 4) =
            make_float4(acc[i][0] + sufv.x, acc[i][1] + sufv.y,
                        acc[i][2] + sufv.z, acc[i][3] + sufv.w);
    }
}

// ---------------------------------------------------------------------------
extern "C" void kernel_launch(void* const* d_in, const int* in_sizes, int n_in,
                              void* d_out, int out_size) {
    const float* X = (const float*)d_in[0];
    // d_in[1] = mask (int32 tril) — structure known, handled analytically
    const float* Wq = (const float*)d_in[2];
    const float* Wk = (const float*)d_in[3];
    const float* Wv = (const float*)d_in[4];
    const float* Wo = (const float*)d_in[5];
    float* Out = (float*)d_out;

    float *Qp, *Kp, *Vp, *Yp;
    cudaGetSymbolAddress((void**)&Qp, g_Q);
    cudaGetSymbolAddress((void**)&Kp, g_K);
    cudaGetSymbolAddress((void**)&Vp, g_V);
    cudaGetSymbolAddress((void**)&Yp, g_Y);

    const int SMEM_SC = (16 * 64 * 33 + 64 * 68 + 32 * 68) * 4;  // 161280 B
    cudaFuncSetAttribute(attn_scores, cudaFuncAttributeMaxDynamicSharedMemorySize, SMEM_SC);

    dim3 gProj(1024 / 64, 2048 / 64);  // (16, 32)
    gemm64<<<gProj, 256>>>(X, Wq, Qp, 1);
    gemm64<<<gProj, 256>>>(X, Wk, Kp, 1);
    gemm64<<<gProj, 256>>>(X, Wv, Vp, 0);

    v_partial<<<dim3(64, 4), 256>>>();
    v_suffix2<<<dim3(64, 4), 256>>>();

    attn_scores<<<dim3(L / 32, L / 64), 256, SMEM_SC>>>();

    attn_av<<<dim3(L / 64, NH), 256>>>();

    gemm64<<<gProj, 256>>>(Yp, Wo, Out, 0);
}

// round 5
// speedup vs baseline: 1.6426x; 1.2790x over previous
#include <cuda_runtime.h>
#include <cuda_bf16.h>
#include <math.h>
#include <stdint.h>

#define L 2048
#define DM 1024
#define NH 16
#define HD 64

// ---------------- Scratch (device globals — no allocation allowed) ----------
__device__ __align__(16) float g_Q[L * DM];
__device__ __align__(16) float g_K[L * DM];
__device__ __align__(16) float g_V[L * DM];
__device__ __align__(16) float g_Y[L * DM];
__device__ __align__(16) float g_part[64 * DM];
__device__ __align__(16) float g_Vsuf[64 * DM];
__device__ __align__(16) float g_A[(size_t)NH * L * L];
// bf16 split operands
__device__ __align__(16) unsigned short g_Ahi[L * DM];
__device__ __align__(16) unsigned short g_Alo[L * DM];
__device__ __align__(16) unsigned short g_Wthi[4 * DM * DM];  // transposed [n][k]
__device__ __align__(16) unsigned short g_Wtlo[4 * DM * DM];

// -log2(500)/64
#define ROPE_LOG2C 0.14009037944784838

__device__ __forceinline__ uint32_t smem_u32(const void* p) {
    uint32_t a;
    asm("{ .reg .u64 t; cvta.to.shared.u64 t, %1; cvt.u32.u64 %0, t; }" : "=r"(a) : "l"(p));
    return a;
}
__device__ __forceinline__ void ldmx4(uint32_t addr, uint32_t& r0, uint32_t& r1,
                                      uint32_t& r2, uint32_t& r3) {
    asm volatile("ldmatrix.sync.aligned.m8n8.x4.shared.b16 {%0,%1,%2,%3}, [%4];"
                 : "=r"(r0), "=r"(r1), "=r"(r2), "=r"(r3) : "r"(addr));
}
__device__ __forceinline__ void ldmx2(uint32_t addr, uint32_t& r0, uint32_t& r1) {
    asm volatile("ldmatrix.sync.aligned.m8n8.x2.shared.b16 {%0,%1}, [%2];"
                 : "=r"(r0), "=r"(r1) : "r"(addr));
}
__device__ __forceinline__ void mma_bf16(float* c, uint32_t a0, uint32_t a1, uint32_t a2,
                                         uint32_t a3, uint32_t b0, uint32_t b1) {
    asm volatile(
        "mma.sync.aligned.m16n8k16.row.col.f32.bf16.bf16.f32 "
        "{%0,%1,%2,%3}, {%4,%5,%6,%7}, {%8,%9}, {%0,%1,%2,%3};"
        : "+f"(c[0]), "+f"(c[1]), "+f"(c[2]), "+f"(c[3])
        : "r"(a0), "r"(a1), "r"(a2), "r"(a3), "r"(b0), "r"(b1));
}

__device__ __forceinline__ unsigned short f2bf(float v) {
    __nv_bfloat16 b = __float2bfloat16(v);
    return *(unsigned short*)&b;
}
__device__ __forceinline__ float bf2f(unsigned short u) {
    __nv_bfloat16 b = *(__nv_bfloat16*)&u;
    return __bfloat162float(b);
}

// ---------------- Prep: split fp32 -> bf16 hi/lo (K-major) ------------------
__global__ __launch_bounds__(256) void xsplit(const float* __restrict__ X,
                                              unsigned short* __restrict__ hi,
                                              unsigned short* __restrict__ lo) {
    size_t i = ((size_t)blockIdx.x * 256 + threadIdx.x) * 4;
    float4 v = *(const float4*)(X + i);
    unsigned short h0 = f2bf(v.x), h1 = f2bf(v.y), h2 = f2bf(v.z), h3 = f2bf(v.w);
    unsigned short l0 = f2bf(v.x - bf2f(h0)), l1 = f2bf(v.y - bf2f(h1));
    unsigned short l2 = f2bf(v.z - bf2f(h2)), l3 = f2bf(v.w - bf2f(h3));
    uint2 uh = make_uint2((uint32_t)h0 | ((uint32_t)h1 << 16), (uint32_t)h2 | ((uint32_t)h3 << 16));
    uint2 ul = make_uint2((uint32_t)l0 | ((uint32_t)l1 << 16), (uint32_t)l2 | ((uint32_t)l3 << 16));
    *(uint2*)(hi + i) = uh;
    *(uint2*)(lo + i) = ul;
}

// ---------------- Prep: transpose W (k,n) -> Wt (n,k), bf16 hi/lo split -----
__global__ __launch_bounds__(256) void wsplit_t(const float* __restrict__ W,
                                                unsigned short* __restrict__ hi,
                                                unsigned short* __restrict__ lo) {
    __shared__ float s[32][33];
    int n0 = blockIdx.x * 32, k0 = blockIdx.y * 32;
    int tx = threadIdx.x & 31, ty = threadIdx.x >> 5;
#pragma unroll
    for (int d = 0; d < 4; d++) {
        int i = ty * 4 + d;
        s[i][tx] = W[(size_t)(k0 + i) * DM + n0 + tx];
    }
    __syncthreads();
#pragma unroll
    for (int d = 0; d < 4; d++) {
        int i = ty * 4 + d;
        float v = s[tx][i];
        unsigned short h = f2bf(v);
        unsigned short l = f2bf(v - bf2f(h));
        hi[(size_t)(n0 + i) * DM + k0 + tx] = h;
        lo[(size_t)(n0 + i) * DM + k0 + tx] = l;
    }
}

// ---------------- HMMA GEMM: C[2048,1024] = A @ Bt^T, 3-term bf16 split -----
// CTA 128x128, BK=32, 8 warps (2 M x 4 N), warp tile 64x32.
// mma.sync m16n8k16 bf16 (arch-portable tensor path; tcgen05 is sm_103a-gated
// and the harness compiles via compute_103).
// ---------------------------------------------------------------------------
__global__ __launch_bounds__(256) void mm_hmma(const unsigned short* __restrict__ Ahi,
                                               const unsigned short* __restrict__ Alo,
                                               const unsigned short* __restrict__ Bhi,
                                               const unsigned short* __restrict__ Blo,
                                               float* __restrict__ C, int doRope) {
    __shared__ __align__(16) unsigned short sAh[128][40];
    __shared__ __align__(16) unsigned short sAl[128][40];
    __shared__ __align__(16) unsigned short sBh[128][40];
    __shared__ __align__(16) unsigned short sBl[128][40];

    const int tid = threadIdx.x;
    const int wid = tid >> 5, lid = tid & 31;
    const int wm = wid & 1, wn = wid >> 1;  // warp: 64 M-rows, 32 N-cols
    const int m0 = blockIdx.y * 128, n0 = blockIdx.x * 128;

    float acc[4][4][4] = {};  // [mtile][ntile][c0..c3]

    // per-lane ldmatrix row offsets (row stride = 80 B)
    const uint32_t aRowOff = (uint32_t)((lid & 15) * 80 + (lid >> 4) * 16);
    const uint32_t bRowOff = (uint32_t)((lid & 7) * 80 + ((lid >> 3) & 1) * 16);
    const uint32_t baseAh = smem_u32(&sAh[wm * 64][0]) + aRowOff;
    const uint32_t baseAl = smem_u32(&sAl[wm * 64][0]) + aRowOff;
    const uint32_t baseBh = smem_u32(&sBh[wn * 32][0]) + bRowOff;
    const uint32_t baseBl = smem_u32(&sBl[wn * 32][0]) + bRowOff;

    for (int k0 = 0; k0 < DM; k0 += 32) {
        __syncthreads();
#pragma unroll
        for (int it = 0; it < 2; it++) {
            int ii = tid + it * 256;          // 0..511
            int row = ii >> 2, ch = ii & 3;   // 4 x 16B per row
            size_t ga = (size_t)(m0 + row) * DM + k0 + ch * 8;
            size_t gb = (size_t)(n0 + row) * DM + k0 + ch * 8;
            *(uint4*)(&sAh[row][ch * 8]) = *(const uint4*)(Ahi + ga);
            *(uint4*)(&sAl[row][ch * 8]) = *(const uint4*)(Alo + ga);
            *(uint4*)(&sBh[row][ch * 8]) = *(const uint4*)(Bhi + gb);
            *(uint4*)(&sBl[row][ch * 8]) = *(const uint4*)(Blo + gb);
        }
        __syncthreads();

#pragma unroll
        for (int ks = 0; ks < 2; ks++) {
            uint32_t bh[4][2], bl[4][2];
#pragma unroll
            for (int j = 0; j < 4; j++) {
                ldmx2(baseBh + j * 640 + ks * 32, bh[j][0], bh[j][1]);
                ldmx2(baseBl + j * 640 + ks * 32, bl[j][0], bl[j][1]);
            }
#pragma unroll
            for (int i = 0; i < 4; i++) {
                uint32_t ah0, ah1, ah2, ah3, al0, al1, al2, al3;
                ldmx4(baseAh + i * 1280 + ks * 32, ah0, ah1, ah2, ah3);
                ldmx4(baseAl + i * 1280 + ks * 32, al0, al1, al2, al3);
#pragma unroll
                for (int j = 0; j < 4; j++) {
                    mma_bf16(acc[i][j], ah0, ah1, ah2, ah3, bh[j][0], bh[j][1]);
                    mma_bf16(acc[i][j], ah0, ah1, ah2, ah3, bl[j][0], bl[j][1]);
                    mma_bf16(acc[i][j], al0, al1, al2, al3, bh[j][0], bh[j][1]);
                }
            }
        }
    }

    // Epilogue: fragment layout c0,c1 at (m, n..n+1), c2,c3 at (m+8, n..n+1)
    const int quad = lid & 3, trow = lid >> 2;
#pragma unroll
    for (int i = 0; i < 4; i++) {
        int m = m0 + wm * 64 + i * 16 + trow;
#pragma unroll
        for (int j = 0; j < 4; j++) {
            int n = n0 + wn * 32 + j * 8 + quad * 2;
            float e0 = acc[i][j][0], o0 = acc[i][j][1];
            float e1 = acc[i][j][2], o1 = acc[i][j][3];
            if (doRope) {
                int t = n & 63;
                float fr = (float)exp2(-(double)t * ROPE_LOG2C);
                float s, c;
                sincosf((float)m * fr, &s, &c);
                float te = e0;
                e0 = te * c - o0 * s;
                o0 = te * s + o0 * c;
                sincosf((float)(m + 8) * fr, &s, &c);
                te = e1;
                e1 = te * c - o1 * s;
                o1 = te * s + o1 * c;
            }
            *(float2*)(C + (size_t)m * DM + n) = make_float2(e0, o0);
            *(float2*)(C + (size_t)(m + 8) * DM + n) = make_float2(e1, o1);
        }
    }
}

// ---------------- V chunk partials + suffix ---------------------------------
__global__ __launch_bounds__(256) void v_partial() {
    int j = blockIdx.x;
    int c = blockIdx.y * 256 + threadIdx.x;
    const float* base = g_V + (size_t)(j * 32) * DM + c;
    float s = 0.f;
#pragma unroll
    for (int r = 0; r < 32; r++) s += base[(size_t)r * DM];
    g_part[(size_t)j * DM + c] = s;
}

__global__ __launch_bounds__(256) void v_suffix2() {
    int j = blockIdx.x;
    int c = blockIdx.y * 256 + threadIdx.x;
    float s = 0.f;
    for (int i = j; i < 64; i++) s += g_part[(size_t)i * DM + c];
    g_Vsuf[(size_t)j * DM + c] = s;
}

// ---------------- Scores + head-axis softmax --------------------------------
__global__ __launch_bounds__(256) void attn_scores() {
    extern __shared__ float smf[];
    float* S = smf;
    float* Qs = smf + 16 * 64 * 33;
    float* Ks = Qs + 64 * 68;

    const int k0 = blockIdx.x * 32;
    const int q0 = blockIdx.y * 64;
    if (k0 >= q0 + 64) return;

    const int tid = threadIdx.x;
    const int tq = tid >> 3, tk = tid & 7;
    const int qiA = tq * 2, kj0 = tk * 4;

    for (int h = 0; h < NH; h++) {
        __syncthreads();
#pragma unroll
        for (int it = 0; it < 4; it++) {
            int idx = tid + it * 256;
            int row = idx >> 4, c4 = idx & 15;
            *(float4*)(Qs + row * 68 + c4 * 4) =
                *(const float4*)(g_Q + (size_t)(q0 + row) * DM + h * HD + c4 * 4);
        }
#pragma unroll
        for (int it = 0; it < 2; it++) {
            int idx = tid + it * 256;
            int row = idx >> 4, c4 = idx & 15;
            *(float4*)(Ks + row * 68 + c4 * 4) =
                *(const float4*)(g_K + (size_t)(k0 + row) * DM + h * HD + c4 * 4);
        }
        __syncthreads();

        float acc[2][4] = {};
#pragma unroll
        for (int c4 = 0; c4 < 16; c4++) {
            float4 qa = *(const float4*)(Qs + qiA * 68 + c4 * 4);
            float4 qb = *(const float4*)(Qs + (qiA + 1) * 68 + c4 * 4);
#pragma unroll
            for (int j = 0; j < 4; j++) {
                float4 kv = *(const float4*)(Ks + (kj0 + j) * 68 + c4 * 4);
                acc[0][j] += qa.x * kv.x + qa.y * kv.y + qa.z * kv.z + qa.w * kv.w;
                acc[1][j] += qb.x * kv.x + qb.y * kv.y + qb.z * kv.z + qb.w * kv.w;
            }
        }
        float* Sh = S + h * (64 * 33);
#pragma unroll
        for (int i = 0; i < 2; i++)
#pragma unroll
            for (int j = 0; j < 4; j++)
                Sh[(qiA + i) * 33 + kj0 + j] = acc[i][j] * 0.125f;
    }
    __syncthreads();

#pragma unroll
    for (int i = 0; i < 2; i++) {
        int qi = qiA + i, q = q0 + qi;
#pragma unroll
        for (int j = 0; j < 4; j++) {
            int kj = kj0 + j, k = k0 + kj;
            float* cell = S + qi * 33 + kj;
            if (k > q) {
#pragma unroll
                for (int h = 0; h < NH; h++) cell[h * (64 * 33)] = 0.0625f;
            } else {
                float mx = -1e30f;
#pragma unroll
                for (int h = 0; h < NH; h++) mx = fmaxf(mx, cell[h * (64 * 33)]);
                float e[NH];
                float sum = 0.f;
#pragma unroll
                for (int h = 0; h < NH; h++) {
                    e[h] = __expf(cell[h * (64 * 33)] - mx);
                    sum += e[h];
                }
                float inv = 1.0f / sum;
#pragma unroll
                for (int h = 0; h < NH; h++) cell[h * (64 * 33)] = e[h] * inv;
            }
        }
    }
    __syncthreads();

    for (int idx = tid; idx < NH * 64 * 32; idx += 256) {
        int h = idx >> 11;
        int rem = idx & 2047;
        int qi = rem >> 5, kj = rem & 31;
        g_A[((size_t)h << 22) + (size_t)(q0 + qi) * L + (k0 + kj)] =
            S[h * (64 * 33) + qi * 33 + kj];
    }
}

// ---------------- AV ---------------------------------------------------------
__global__ __launch_bounds__(256) void attn_av() {
    __shared__ float As[32][65];
    __shared__ float Bs[32][68];

    const int q0 = blockIdx.x * 64;
    const int h = blockIdx.y;
    const int tid = threadIdx.x;
    const int ty = tid >> 4, tx = tid & 15;
    const int klim = (q0 + 64 < L) ? (q0 + 64) : L;

    const float* Abase = g_A + ((size_t)h << 22);
    float acc[4][4] = {};

    for (int k0 = 0; k0 < klim; k0 += 32) {
        __syncthreads();
#pragma unroll
        for (int it = 0; it < 2; it++) {
            int idx = tid + it * 256;
            int r = idx >> 3, c4 = idx & 7;
            float4 av = *(const float4*)(Abase + (size_t)(q0 + r) * L + k0 + c4 * 4);
            As[c4 * 4 + 0][r] = av.x;
            As[c4 * 4 + 1][r] = av.y;
            As[c4 * 4 + 2][r] = av.z;
            As[c4 * 4 + 3][r] = av.w;
        }
#pragma unroll
        for (int it = 0; it < 2; it++) {
            int idx = tid + it * 256;
            int r = idx >> 4, c4 = idx & 15;
            *(float4*)(&Bs[r][c4 * 4]) =
                *(const float4*)(g_V + (size_t)(k0 + r) * DM + h * HD + c4 * 4);
        }
        __syncthreads();
#pragma unroll
        for (int kk = 0; kk < 32; kk++) {
            float a[4];
#pragma unroll
            for (int i = 0; i < 4; i++) a[i] = As[kk][ty * 4 + i];
            float4 b = *(const float4*)(&Bs[kk][tx * 4]);
#pragma unroll
            for (int i = 0; i < 4; i++) {
                acc[i][0] += a[i] * b.x;
                acc[i][1] += a[i] * b.y;
                acc[i][2] += a[i] * b.z;
                acc[i][3] += a[i] * b.w;
            }
        }
    }

    float4 sufv = make_float4(0.f, 0.f, 0.f, 0.f);
    if (klim < L) {
        float4 v = *(const float4*)(g_Vsuf + (size_t)(klim >> 5) * DM + h * HD + tx * 4);
        sufv = make_float4(0.0625f * v.x, 0.0625f * v.y, 0.0625f * v.z, 0.0625f * v.w);
    }
#pragma unroll
    for (int i = 0; i < 4; i++) {
        int m = q0 + ty * 4 + i;
        *(float4*)(g_Y + (size_t)m * DM + h * HD + tx * 4) =
            make_float4(acc[i][0] + sufv.x, acc[i][1] + sufv.y,
                        acc[i][2] + sufv.z, acc[i][3] + sufv.w);
    }
}

// ---------------------------------------------------------------------------
extern "C" void kernel_launch(void* const* d_in, const int* in_sizes, int n_in,
                              void* d_out, int out_size) {
    const float* X = (const float*)d_in[0];
    const float* Wq = (const float*)d_in[2];
    const float* Wk = (const float*)d_in[3];
    const float* Wv = (const float*)d_in[4];
    const float* Wo = (const float*)d_in[5];
    float* Out = (float*)d_out;

    float *Qp, *Kp, *Vp, *Yp;
    unsigned short *Ahip, *Alop, *Wthip, *Wtlop;
    cudaGetSymbolAddress((void**)&Qp, g_Q);
    cudaGetSymbolAddress((void**)&Kp, g_K);
    cudaGetSymbolAddress((void**)&Vp, g_V);
    cudaGetSymbolAddress((void**)&Yp, g_Y);
    cudaGetSymbolAddress((void**)&Ahip, g_Ahi);
    cudaGetSymbolAddress((void**)&Alop, g_Alo);
    cudaGetSymbolAddress((void**)&Wthip, g_Wthi);
    cudaGetSymbolAddress((void**)&Wtlop, g_Wtlo);

    const int SMEM_SC = (16 * 64 * 33 + 64 * 68 + 32 * 68) * 4;  // 161280 B
    cudaFuncSetAttribute(attn_scores, cudaFuncAttributeMaxDynamicSharedMemorySize, SMEM_SC);

    const size_t WSZ = (size_t)DM * DM;
    dim3 gW(DM / 32, DM / 32);
    wsplit_t<<<gW, 256>>>(Wq, Wthip + 0 * WSZ, Wtlop + 0 * WSZ);
    wsplit_t<<<gW, 256>>>(Wk, Wthip + 1 * WSZ, Wtlop + 1 * WSZ);
    wsplit_t<<<gW, 256>>>(Wv, Wthip + 2 * WSZ, Wtlop + 2 * WSZ);
    wsplit_t<<<gW, 256>>>(Wo, Wthip + 3 * WSZ, Wtlop + 3 * WSZ);

    xsplit<<<(L * DM) / 1024, 256>>>(X, Ahip, Alop);

    dim3 gMM(DM / 128, L / 128);  // (8, 16)
    mm_hmma<<<gMM, 256>>>(Ahip, Alop, Wthip + 0 * WSZ, Wtlop + 0 * WSZ, Qp, 1);
    mm_hmma<<<gMM, 256>>>(Ahip, Alop, Wthip + 1 * WSZ, Wtlop + 1 * WSZ, Kp, 1);
    mm_hmma<<<gMM, 256>>>(Ahip, Alop, Wthip + 2 * WSZ, Wtlop + 2 * WSZ, Vp, 0);

    v_partial<<<dim3(64, 4), 256>>>();
    v_suffix2<<<dim3(64, 4), 256>>>();

    attn_scores<<<dim3(L / 32, L / 64), 256, SMEM_SC>>>();
    attn_av<<<dim3(L / 64, NH), 256>>>();

    xsplit<<<(L * DM) / 1024, 256>>>(Yp, Ahip, Alop);
    mm_hmma<<<gMM, 256>>>(Ahip, Alop, Wthip + 3 * WSZ, Wtlop + 3 * WSZ, Out, 0);
}

// round 6
// speedup vs baseline: 3.1232x; 1.9013x over previous
#include <cuda_runtime.h>
#include <cuda_bf16.h>
#include <math.h>
#include <stdint.h>

#define L 2048
#define DM 1024
#define NH 16
#define HD 64

// ---------------- Scratch (device globals — no allocation allowed) ----------
__device__ __align__(16) float g_V[L * DM];
__device__ __align__(16) float g_part[64 * DM];
__device__ __align__(16) float g_Vsuf[64 * DM];
__device__ __align__(16) float g_A[(size_t)NH * L * L];  // fp32 head-softmaxed weights
__device__ __align__(16) unsigned short g_Xhi[L * DM];   // bf16 hi/lo of X (and reused? no - X only)
__device__ __align__(16) unsigned short g_Xlo[L * DM];
__device__ __align__(16) unsigned short g_Yhi[L * DM];   // bf16 hi/lo of attention output Y
__device__ __align__(16) unsigned short g_Ylo[L * DM];
__device__ __align__(16) unsigned short g_Qhi[L * DM];
__device__ __align__(16) unsigned short g_Qlo[L * DM];
__device__ __align__(16) unsigned short g_Khi[L * DM];
__device__ __align__(16) unsigned short g_Klo[L * DM];
__device__ __align__(16) unsigned short g_Vhi[L * DM];
__device__ __align__(16) unsigned short g_Vlo[L * DM];
__device__ __align__(16) unsigned short g_Wthi[4 * DM * DM];  // W^T [n][k]
__device__ __align__(16) unsigned short g_Wtlo[4 * DM * DM];

// -log2(500)/64
#define ROPE_LOG2C 0.14009037944784838

__device__ __forceinline__ uint32_t smem_u32(const void* p) {
    uint32_t a;
    asm("{ .reg .u64 t; cvta.to.shared.u64 t, %1; cvt.u32.u64 %0, t; }" : "=r"(a) : "l"(p));
    return a;
}
__device__ __forceinline__ void ldmx4(uint32_t addr, uint32_t& r0, uint32_t& r1,
                                      uint32_t& r2, uint32_t& r3) {
    asm volatile("ldmatrix.sync.aligned.m8n8.x4.shared.b16 {%0,%1,%2,%3}, [%4];"
                 : "=r"(r0), "=r"(r1), "=r"(r2), "=r"(r3) : "r"(addr));
}
__device__ __forceinline__ void ldmx4t(uint32_t addr, uint32_t& r0, uint32_t& r1,
                                       uint32_t& r2, uint32_t& r3) {
    asm volatile("ldmatrix.sync.aligned.m8n8.x4.trans.shared.b16 {%0,%1,%2,%3}, [%4];"
                 : "=r"(r0), "=r"(r1), "=r"(r2), "=r"(r3) : "r"(addr));
}
__device__ __forceinline__ void ldmx2(uint32_t addr, uint32_t& r0, uint32_t& r1) {
    asm volatile("ldmatrix.sync.aligned.m8n8.x2.shared.b16 {%0,%1}, [%2];"
                 : "=r"(r0), "=r"(r1) : "r"(addr));
}
__device__ __forceinline__ void mma_bf16(float* c, uint32_t a0, uint32_t a1, uint32_t a2,
                                         uint32_t a3, uint32_t b0, uint32_t b1) {
    asm volatile(
        "mma.sync.aligned.m16n8k16.row.col.f32.bf16.bf16.f32 "
        "{%0,%1,%2,%3}, {%4,%5,%6,%7}, {%8,%9}, {%0,%1,%2,%3};"
        : "+f"(c[0]), "+f"(c[1]), "+f"(c[2]), "+f"(c[3])
        : "r"(a0), "r"(a1), "r"(a2), "r"(a3), "r"(b0), "r"(b1));
}

__device__ __forceinline__ unsigned short f2bf(float v) {
    __nv_bfloat16 b = __float2bfloat16(v);
    return *(unsigned short*)&b;
}
__device__ __forceinline__ float bf2f(unsigned short u) {
    __nv_bfloat16 b = *(__nv_bfloat16*)&u;
    return __bfloat162float(b);
}

// ---------------- Prep: split fp32 -> bf16 hi/lo ----------------------------
__global__ __launch_bounds__(256) void xsplit(const float* __restrict__ X,
                                              unsigned short* __restrict__ hi,
                                              unsigned short* __restrict__ lo) {
    size_t i = ((size_t)blockIdx.x * 256 + threadIdx.x) * 4;
    float4 v = *(const float4*)(X + i);
    unsigned short h0 = f2bf(v.x), h1 = f2bf(v.y), h2 = f2bf(v.z), h3 = f2bf(v.w);
    unsigned short l0 = f2bf(v.x - bf2f(h0)), l1 = f2bf(v.y - bf2f(h1));
    unsigned short l2 = f2bf(v.z - bf2f(h2)), l3 = f2bf(v.w - bf2f(h3));
    *(uint2*)(hi + i) = make_uint2((uint32_t)h0 | ((uint32_t)h1 << 16),
                                   (uint32_t)h2 | ((uint32_t)h3 << 16));
    *(uint2*)(lo + i) = make_uint2((uint32_t)l0 | ((uint32_t)l1 << 16),
                                   (uint32_t)l2 | ((uint32_t)l3 << 16));
}

// ---------------- Prep: transpose W -> Wt (n,k), bf16 hi/lo split ------------
__global__ __launch_bounds__(256) void wsplit_t(const float* __restrict__ W,
                                                unsigned short* __restrict__ hi,
                                                unsigned short* __restrict__ lo) {
    __shared__ float s[32][33];
    int n0 = blockIdx.x * 32, k0 = blockIdx.y * 32;
    int tx = threadIdx.x & 31, ty = threadIdx.x >> 5;
#pragma unroll
    for (int d = 0; d < 4; d++) {
        int i = ty * 4 + d;
        s[i][tx] = W[(size_t)(k0 + i) * DM + n0 + tx];
    }
    __syncthreads();
#pragma unroll
    for (int d = 0; d < 4; d++) {
        int i = ty * 4 + d;
        float v = s[tx][i];
        unsigned short h = f2bf(v);
        unsigned short l = f2bf(v - bf2f(h));
        hi[(size_t)(n0 + i) * DM + k0 + tx] = h;
        lo[(size_t)(n0 + i) * DM + k0 + tx] = l;
    }
}

// ---------------- HMMA GEMM with flexible epilogue ---------------------------
// C = A @ Bt^T, 3-term bf16 split. CTA 128x128, BK=32, 8 warps (2M x 4N).
// Epilogue: optional RoPE; writes fp32 (Cf) and/or bf16 hi/lo (Chi/Clo).
__global__ __launch_bounds__(256) void mm_hmma(const unsigned short* __restrict__ Ahi,
                                               const unsigned short* __restrict__ Alo,
                                               const unsigned short* __restrict__ Bhi,
                                               const unsigned short* __restrict__ Blo,
                                               float* __restrict__ Cf,
                                               unsigned short* __restrict__ Chi,
                                               unsigned short* __restrict__ Clo,
                                               int doRope) {
    __shared__ __align__(16) unsigned short sAh[128][40];
    __shared__ __align__(16) unsigned short sAl[128][40];
    __shared__ __align__(16) unsigned short sBh[128][40];
    __shared__ __align__(16) unsigned short sBl[128][40];

    const int tid = threadIdx.x;
    const int wid = tid >> 5, lid = tid & 31;
    const int wm = wid & 1, wn = wid >> 1;
    const int m0 = blockIdx.y * 128, n0 = blockIdx.x * 128;

    float acc[4][4][4] = {};

    const uint32_t aRowOff = (uint32_t)((lid & 15) * 80 + (lid >> 4) * 16);
    const uint32_t bRowOff = (uint32_t)((lid & 7) * 80 + ((lid >> 3) & 1) * 16);
    const uint32_t baseAh = smem_u32(&sAh[wm * 64][0]) + aRowOff;
    const uint32_t baseAl = smem_u32(&sAl[wm * 64][0]) + aRowOff;
    const uint32_t baseBh = smem_u32(&sBh[wn * 32][0]) + bRowOff;
    const uint32_t baseBl = smem_u32(&sBl[wn * 32][0]) + bRowOff;

    for (int k0 = 0; k0 < DM; k0 += 32) {
        __syncthreads();
#pragma unroll
        for (int it = 0; it < 2; it++) {
            int ii = tid + it * 256;
            int row = ii >> 2, ch = ii & 3;
            size_t ga = (size_t)(m0 + row) * DM + k0 + ch * 8;
            size_t gb = (size_t)(n0 + row) * DM + k0 + ch * 8;
            *(uint4*)(&sAh[row][ch * 8]) = *(const uint4*)(Ahi + ga);
            *(uint4*)(&sAl[row][ch * 8]) = *(const uint4*)(Alo + ga);
            *(uint4*)(&sBh[row][ch * 8]) = *(const uint4*)(Bhi + gb);
            *(uint4*)(&sBl[row][ch * 8]) = *(const uint4*)(Blo + gb);
        }
        __syncthreads();

#pragma unroll
        for (int ks = 0; ks < 2; ks++) {
            uint32_t bh[4][2], bl[4][2];
#pragma unroll
            for (int j = 0; j < 4; j++) {
                ldmx2(baseBh + j * 640 + ks * 32, bh[j][0], bh[j][1]);
                ldmx2(baseBl + j * 640 + ks * 32, bl[j][0], bl[j][1]);
            }
#pragma unroll
            for (int i = 0; i < 4; i++) {
                uint32_t ah0, ah1, ah2, ah3, al0, al1, al2, al3;
                ldmx4(baseAh + i * 1280 + ks * 32, ah0, ah1, ah2, ah3);
                ldmx4(baseAl + i * 1280 + ks * 32, al0, al1, al2, al3);
#pragma unroll
                for (int j = 0; j < 4; j++) {
                    mma_bf16(acc[i][j], ah0, ah1, ah2, ah3, bh[j][0], bh[j][1]);
                    mma_bf16(acc[i][j], ah0, ah1, ah2, ah3, bl[j][0], bl[j][1]);
                    mma_bf16(acc[i][j], al0, al1, al2, al3, bh[j][0], bh[j][1]);
                }
            }
        }
    }

    const int quad = lid & 3, trow = lid >> 2;
#pragma unroll
    for (int i = 0; i < 4; i++) {
        int mA = m0 + wm * 64 + i * 16 + trow;
#pragma unroll
        for (int j = 0; j < 4; j++) {
            int n = n0 + wn * 32 + j * 8 + quad * 2;
            float e0 = acc[i][j][0], o0 = acc[i][j][1];
            float e1 = acc[i][j][2], o1 = acc[i][j][3];
            if (doRope) {
                int t = n & 63;
                float fr = (float)exp2(-(double)t * ROPE_LOG2C);
                float s, c;
                sincosf((float)mA * fr, &s, &c);
                float te = e0;
                e0 = te * c - o0 * s;
                o0 = te * s + o0 * c;
                sincosf((float)(mA + 8) * fr, &s, &c);
                te = e1;
                e1 = te * c - o1 * s;
                o1 = te * s + o1 * c;
            }
            size_t p0 = (size_t)mA * DM + n, p1 = (size_t)(mA + 8) * DM + n;
            if (Cf) {
                *(float2*)(Cf + p0) = make_float2(e0, o0);
                *(float2*)(Cf + p1) = make_float2(e1, o1);
            }
            if (Chi) {
                unsigned short he0 = f2bf(e0), ho0 = f2bf(o0);
                unsigned short he1 = f2bf(e1), ho1 = f2bf(o1);
                *(uint32_t*)(Chi + p0) = (uint32_t)he0 | ((uint32_t)ho0 << 16);
                *(uint32_t*)(Chi + p1) = (uint32_t)he1 | ((uint32_t)ho1 << 16);
                unsigned short le0 = f2bf(e0 - bf2f(he0)), lo0 = f2bf(o0 - bf2f(ho0));
                unsigned short le1 = f2bf(e1 - bf2f(he1)), lo1 = f2bf(o1 - bf2f(ho1));
                *(uint32_t*)(Clo + p0) = (uint32_t)le0 | ((uint32_t)lo0 << 16);
                *(uint32_t*)(Clo + p1) = (uint32_t)le1 | ((uint32_t)lo1 << 16);
            }
        }
    }
}

// ---------------- V chunk partials + suffix ---------------------------------
__global__ __launch_bounds__(256) void v_partial() {
    int j = blockIdx.x;
    int c = blockIdx.y * 256 + threadIdx.x;
    const float* base = g_V + (size_t)(j * 32) * DM + c;
    float s = 0.f;
#pragma unroll
    for (int r = 0; r < 32; r++) s += base[(size_t)r * DM];
    g_part[(size_t)j * DM + c] = s;
}
__global__ __launch_bounds__(256) void v_suffix2() {
    int j = blockIdx.x;
    int c = blockIdx.y * 256 + threadIdx.x;
    float s = 0.f;
    for (int i = j; i < 64; i++) s += g_part[(size_t)i * DM + c];
    g_Vsuf[(size_t)j * DM + c] = s;
}

// ---------------- Scores (HMMA) + head-axis softmax --------------------------
// CTA 32q x 64k, all 16 heads. S staged fp32 in smem [16][32][66].
// 3-term split S = Q·K^T per head, softmax over h, fp32 A writeback.
#define S_STRIDE 66
#define S_HEAD (32 * S_STRIDE)
__global__ __launch_bounds__(256) void attn_sc() {
    extern __shared__ char sms[];
    float* S = (float*)sms;                                      // 135168 B
    unsigned short* Qh = (unsigned short*)(sms + 135168);        // 32x72
    unsigned short* Ql = Qh + 32 * 72;
    unsigned short* Kh = Ql + 32 * 72;                           // 64x72
    unsigned short* Kl = Kh + 64 * 72;

    const int k0 = blockIdx.x * 64;
    const int q0 = blockIdx.y * 32;
    if (k0 >= (q0 & ~63) + 64) return;  // beyond the AV 64-row tile's k range

    const int tid = threadIdx.x;
    const int wid = tid >> 5, lid = tid & 31;
    const int wm = wid & 1, wn = wid >> 1;  // warp tile 16q x 16k
    const int trow = lid >> 2, quad = lid & 3;

    const uint32_t aOff = (uint32_t)((lid & 15) * 144 + (lid >> 4) * 16);
    const uint32_t bOff = (uint32_t)((lid & 7) * 144 + ((lid >> 3) & 1) * 16);
    const uint32_t baseQh = smem_u32(Qh) + wm * 16 * 144 + aOff;
    const uint32_t baseQl = smem_u32(Ql) + wm * 16 * 144 + aOff;
    const uint32_t baseKh = smem_u32(Kh) + wn * 16 * 144 + bOff;
    const uint32_t baseKl = smem_u32(Kl) + wn * 16 * 144 + bOff;

    const int lr = tid >> 3, lch = tid & 7;  // loader: row, 16B chunk

    for (int h = 0; h < NH; h++) {
        __syncthreads();
        {  // Q: 32 rows x 8 chunks = 256 slots (1 per thread, hi & lo)
            size_t g = (size_t)(q0 + lr) * DM + h * HD + lch * 8;
            *(uint4*)((char*)Qh + lr * 144 + lch * 16) = *(const uint4*)(g_Qhi + g);
            *(uint4*)((char*)Ql + lr * 144 + lch * 16) = *(const uint4*)(g_Qlo + g);
        }
#pragma unroll
        for (int it = 0; it < 2; it++) {  // K: 64 rows x 8 chunks = 512 slots
            int ii = tid + it * 256;
            int rr = ii >> 3, ch = ii & 7;
            size_t g = (size_t)(k0 + rr) * DM + h * HD + ch * 8;
            *(uint4*)((char*)Kh + rr * 144 + ch * 16) = *(const uint4*)(g_Khi + g);
            *(uint4*)((char*)Kl + rr * 144 + ch * 16) = *(const uint4*)(g_Klo + g);
        }
        __syncthreads();

        float acc[2][4] = {};
#pragma unroll
        for (int ks = 0; ks < 4; ks++) {  // d = 64 -> 4 k16 steps (32B each)
            uint32_t qh0, qh1, qh2, qh3, ql0, ql1, ql2, ql3;
            ldmx4(baseQh + ks * 32, qh0, qh1, qh2, qh3);
            ldmx4(baseQl + ks * 32, ql0, ql1, ql2, ql3);
#pragma unroll
            for (int nf = 0; nf < 2; nf++) {
                uint32_t kh0, kh1, kl0, kl1;
                ldmx2(baseKh + nf * 1152 + ks * 32, kh0, kh1);
                ldmx2(baseKl + nf * 1152 + ks * 32, kl0, kl1);
                mma_bf16(acc[nf], qh0, qh1, qh2, qh3, kh0, kh1);
                mma_bf16(acc[nf], qh0, qh1, qh2, qh3, kl0, kl1);
                mma_bf16(acc[nf], ql0, ql1, ql2, ql3, kh0, kh1);
            }
        }
        float* Sh = S + h * S_HEAD;
#pragma unroll
        for (int nf = 0; nf < 2; nf++) {
            int row = wm * 16 + trow, col = wn * 16 + nf * 8 + quad * 2;
            Sh[row * S_STRIDE + col] = acc[nf][0] * 0.125f;
            Sh[row * S_STRIDE + col + 1] = acc[nf][1] * 0.125f;
            Sh[(row + 8) * S_STRIDE + col] = acc[nf][2] * 0.125f;
            Sh[(row + 8) * S_STRIDE + col + 1] = acc[nf][3] * 0.125f;
        }
    }
    __syncthreads();

    // Head-axis softmax per (q,k) cell
#pragma unroll
    for (int it = 0; it < 8; it++) {
        int idx = tid + it * 256;
        int row = idx >> 6, col = idx & 63;
        int q = q0 + row, k = k0 + col;
        float* cell = S + row * S_STRIDE + col;
        if (k > q) {
#pragma unroll
            for (int h = 0; h < NH; h++) cell[h * S_HEAD] = 0.0625f;
        } else {
            float e[NH], mx = -1e30f;
#pragma unroll
            for (int h = 0; h < NH; h++) {
                e[h] = cell[h * S_HEAD];
                mx = fmaxf(mx, e[h]);
            }
            float sum = 0.f;
#pragma unroll
            for (int h = 0; h < NH; h++) {
                e[h] = __expf(e[h] - mx);
                sum += e[h];
            }
            float inv = 1.0f / sum;
#pragma unroll
            for (int h = 0; h < NH; h++) cell[h * S_HEAD] = e[h] * inv;
        }
    }
    __syncthreads();

    // Coalesced fp32 writeback: 16*32*64 = 32768 values
    for (int it = 0; it < 128; it++) {
        int idx = tid + it * 256;
        int h = idx >> 11;
        int rem = idx & 2047;
        int row = rem >> 6, col = rem & 63;
        g_A[((size_t)h << 22) + (size_t)(q0 + row) * L + (k0 + col)] =
            S[h * S_HEAD + row * S_STRIDE + col];
    }
}

// ---------------- AV (HMMA): Y = A·V + (1/16)·Vsuf tail ----------------------
// CTA = (64q tile, head). A fp32 -> hi/lo split in-kernel. V via ldmatrix.trans.
// Output written directly as bf16 hi/lo of Y (input to the Wo GEMM).
__global__ __launch_bounds__(256) void attn_av() {
    __shared__ __align__(16) unsigned short sAh[64 * 40];  // 64q x 32k
    __shared__ __align__(16) unsigned short sAl[64 * 40];
    __shared__ __align__(16) unsigned short sVh[32 * 72];  // 32k x 64d
    __shared__ __align__(16) unsigned short sVl[32 * 72];

    const int q0 = blockIdx.x * 64;
    const int h = blockIdx.y;
    const int tid = threadIdx.x;
    const int wid = tid >> 5, lid = tid & 31;
    const int wm = wid & 1, wn = wid >> 1;  // warp tile 32q x 16d
    const int klim = q0 + 64;

    const float* Abase = g_A + ((size_t)h << 22);
    float acc[2][2][4] = {};  // [mf][nf][4]

    const uint32_t aOff = (uint32_t)((lid & 15) * 80 + (lid >> 4) * 16);
    const uint32_t vOff =
        (uint32_t)((lid & 7) * 144 + ((lid >> 3) & 1) * 1152 + (lid >> 4) * 16);
    const uint32_t baseAh = smem_u32(sAh) + wm * 32 * 80 + aOff;
    const uint32_t baseAl = smem_u32(sAl) + wm * 32 * 80 + aOff;
    const uint32_t baseVh = smem_u32(sVh) + wn * 32 + vOff;  // wn*16 cols * 2B
    const uint32_t baseVl = smem_u32(sVl) + wn * 32 + vOff;

    const int vr = tid >> 3, vch = tid & 7;

    for (int k0 = 0; k0 < klim; k0 += 32) {
        __syncthreads();
#pragma unroll
        for (int it = 0; it < 2; it++) {  // A: 64 rows x 8 float4 = 512 slots
            int ii = tid + it * 256;
            int r = ii >> 3, ch = ii & 7;
            float4 v = *(const float4*)(Abase + (size_t)(q0 + r) * L + k0 + ch * 4);
            unsigned short h0 = f2bf(v.x), h1 = f2bf(v.y), h2 = f2bf(v.z), h3 = f2bf(v.w);
            unsigned short l0 = f2bf(v.x - bf2f(h0)), l1 = f2bf(v.y - bf2f(h1));
            unsigned short l2 = f2bf(v.z - bf2f(h2)), l3 = f2bf(v.w - bf2f(h3));
            *(uint2*)((char*)sAh + r * 80 + ch * 8) =
                make_uint2((uint32_t)h0 | ((uint32_t)h1 << 16), (uint32_t)h2 | ((uint32_t)h3 << 16));
            *(uint2*)((char*)sAl + r * 80 + ch * 8) =
                make_uint2((uint32_t)l0 | ((uint32_t)l1 << 16), (uint32_t)l2 | ((uint32_t)l3 << 16));
        }
        {  // V: 32 rows x 8 chunks = 256 slots
            size_t g = (size_t)(k0 + vr) * DM + h * HD + vch * 8;
            *(uint4*)((char*)sVh + vr * 144 + vch * 16) = *(const uint4*)(g_Vhi + g);
            *(uint4*)((char*)sVl + vr * 144 + vch * 16) = *(const uint4*)(g_Vlo + g);
        }
        __syncthreads();

#pragma unroll
        for (int ks = 0; ks < 2; ks++) {
            uint32_t vh0, vh1, vh2, vh3, vl0, vl1, vl2, vl3;
            ldmx4t(baseVh + ks * 2304, vh0, vh1, vh2, vh3);  // 16 k-rows * 144B
            ldmx4t(baseVl + ks * 2304, vl0, vl1, vl2, vl3);
#pragma unroll
            for (int mf = 0; mf < 2; mf++) {
                uint32_t ah0, ah1, ah2, ah3, al0, al1, al2, al3;
                ldmx4(baseAh + mf * 1280 + ks * 32, ah0, ah1, ah2, ah3);
                ldmx4(baseAl + mf * 1280 + ks * 32, al0, al1, al2, al3);
                mma_bf16(acc[mf][0], ah0, ah1, ah2, ah3, vh0, vh1);
                mma_bf16(acc[mf][0], ah0, ah1, ah2, ah3, vl0, vl1);
                mma_bf16(acc[mf][0], al0, al1, al2, al3, vh0, vh1);
                mma_bf16(acc[mf][1], ah0, ah1, ah2, ah3, vh2, vh3);
                mma_bf16(acc[mf][1], ah0, ah1, ah2, ah3, vl2, vl3);
                mma_bf16(acc[mf][1], al0, al1, al2, al3, vh2, vh3);
            }
        }
    }

    // Epilogue: masked tail + write Y as bf16 hi/lo
    const int trow = lid >> 2, quad = lid & 3;
#pragma unroll
    for (int nf = 0; nf < 2; nf++) {
        int dc = wn * 16 + nf * 8 + quad * 2;
        float s0 = 0.f, s1 = 0.f;
        if (klim < L) {
            const float* sb = g_Vsuf + (size_t)(klim >> 5) * DM + h * HD;
            s0 = sb[dc] * 0.0625f;
            s1 = sb[dc + 1] * 0.0625f;
        }
#pragma unroll
        for (int mf = 0; mf < 2; mf++) {
            int m = q0 + wm * 32 + mf * 16 + trow;
            float y00 = acc[mf][nf][0] + s0, y01 = acc[mf][nf][1] + s1;
            float y10 = acc[mf][nf][2] + s0, y11 = acc[mf][nf][3] + s1;
            size_t p0 = (size_t)m * DM + h * HD + dc;
            size_t p1 = (size_t)(m + 8) * DM + h * HD + dc;
            unsigned short h00 = f2bf(y00), h01 = f2bf(y01);
            unsigned short h10 = f2bf(y10), h11 = f2bf(y11);
            *(uint32_t*)(g_Yhi + p0) = (uint32_t)h00 | ((uint32_t)h01 << 16);
            *(uint32_t*)(g_Yhi + p1) = (uint32_t)h10 | ((uint32_t)h11 << 16);
            unsigned short l00 = f2bf(y00 - bf2f(h00)), l01 = f2bf(y01 - bf2f(h01));
            unsigned short l10 = f2bf(y10 - bf2f(h10)), l11 = f2bf(y11 - bf2f(h11));
            *(uint32_t*)(g_Ylo + p0) = (uint32_t)l00 | ((uint32_t)l01 << 16);
            *(uint32_t*)(g_Ylo + p1) = (uint32_t)l10 | ((uint32_t)l11 << 16);
        }
    }
}

// ---------------------------------------------------------------------------
extern "C" void kernel_launch(void* const* d_in, const int* in_sizes, int n_in,
                              void* d_out, int out_size) {
    const float* X = (const float*)d_in[0];
    const float* Wq = (const float*)d_in[2];
    const float* Wk = (const float*)d_in[3];
    const float* Wv = (const float*)d_in[4];
    const float* Wo = (const float*)d_in[5];
    float* Out = (float*)d_out;

    float* Vp;
    unsigned short *Xhi, *Xlo, *Yhi, *Ylo, *Qhi, *Qlo, *Khi, *Klo, *Vhi, *Vlo, *Wth, *Wtl;
    cudaGetSymbolAddress((void**)&Vp, g_V);
    cudaGetSymbolAddress((void**)&Xhi, g_Xhi);
    cudaGetSymbolAddress((void**)&Xlo, g_Xlo);
    cudaGetSymbolAddress((void**)&Yhi, g_Yhi);
    cudaGetSymbolAddress((void**)&Ylo, g_Ylo);
    cudaGetSymbolAddress((void**)&Qhi, g_Qhi);
    cudaGetSymbolAddress((void**)&Qlo, g_Qlo);
    cudaGetSymbolAddress((void**)&Khi, g_Khi);
    cudaGetSymbolAddress((void**)&Klo, g_Klo);
    cudaGetSymbolAddress((void**)&Vhi, g_Vhi);
    cudaGetSymbolAddress((void**)&Vlo, g_Vlo);
    cudaGetSymbolAddress((void**)&Wth, g_Wthi);
    cudaGetSymbolAddress((void**)&Wtl, g_Wtlo);

    const int SMEM_SC = 135168 + 2 * 4608 + 2 * 9216;  // 162816 B
    cudaFuncSetAttribute(attn_sc, cudaFuncAttributeMaxDynamicSharedMemorySize, SMEM_SC);

    const size_t WSZ = (size_t)DM * DM;
    dim3 gW(DM / 32, DM / 32);
    wsplit_t<<<gW, 256>>>(Wq, Wth + 0 * WSZ, Wtl + 0 * WSZ);
    wsplit_t<<<gW, 256>>>(Wk, Wth + 1 * WSZ, Wtl + 1 * WSZ);
    wsplit_t<<<gW, 256>>>(Wv, Wth + 2 * WSZ, Wtl + 2 * WSZ);
    wsplit_t<<<gW, 256>>>(Wo, Wth + 3 * WSZ, Wtl + 3 * WSZ);

    xsplit<<<(L * DM) / 1024, 256>>>(X, Xhi, Xlo);

    dim3 gMM(DM / 128, L / 128);  // (8, 16)
    mm_hmma<<<gMM, 256>>>(Xhi, Xlo, Wth + 0 * WSZ, Wtl + 0 * WSZ, nullptr, Qhi, Qlo, 1);
    mm_hmma<<<gMM, 256>>>(Xhi, Xlo, Wth + 1 * WSZ, Wtl + 1 * WSZ, nullptr, Khi, Klo, 1);
    mm_hmma<<<gMM, 256>>>(Xhi, Xlo, Wth + 2 * WSZ, Wtl + 2 * WSZ, Vp, Vhi, Vlo, 0);

    v_partial<<<dim3(64, 4), 256>>>();
    v_suffix2<<<dim3(64, 4), 256>>>();

    attn_sc<<<dim3(L / 64, L / 32), 256, SMEM_SC>>>();
    attn_av<<<dim3(L / 64, NH), 256>>>();

    mm_hmma<<<gMM, 256>>>(Yhi, Ylo, Wth + 3 * WSZ, Wtl + 3 * WSZ, Out, nullptr, nullptr, 0);
}

// round 7
// speedup vs baseline: 3.7257x; 1.1929x over previous
#include <cuda_runtime.h>
#include <cuda_bf16.h>
#include <math.h>
#include <stdint.h>

#define L 2048
#define DM 1024
#define NH 16
#define HD 64

// ---------------- Scratch (device globals — no allocation allowed) ----------
__device__ __align__(16) float g_V[L * DM];
__device__ __align__(16) float g_part[64 * DM];
__device__ __align__(16) float g_Vsuf[64 * DM];
__device__ __align__(16) float g_A[(size_t)NH * L * L];  // fp32 head-softmaxed weights
__device__ __align__(16) unsigned short g_Xhi[L * DM];
__device__ __align__(16) unsigned short g_Xlo[L * DM];
__device__ __align__(16) unsigned short g_Yhi[L * DM];
__device__ __align__(16) unsigned short g_Ylo[L * DM];
__device__ __align__(16) unsigned short g_Qhi[L * DM];
__device__ __align__(16) unsigned short g_Qlo[L * DM];
__device__ __align__(16) unsigned short g_Khi[L * DM];
__device__ __align__(16) unsigned short g_Klo[L * DM];
__device__ __align__(16) unsigned short g_Vhi[L * DM];
__device__ __align__(16) unsigned short g_Vlo[L * DM];
__device__ __align__(16) unsigned short g_Wthi[4 * DM * DM];  // W^T [n][k]
__device__ __align__(16) unsigned short g_Wtlo[4 * DM * DM];

// -log2(500)/64
#define ROPE_LOG2C 0.14009037944784838

__device__ __forceinline__ uint32_t smem_u32(const void* p) {
    uint32_t a;
    asm("{ .reg .u64 t; cvta.to.shared.u64 t, %1; cvt.u32.u64 %0, t; }" : "=r"(a) : "l"(p));
    return a;
}
__device__ __forceinline__ void cp16(uint32_t saddr, const void* gaddr) {
    asm volatile("cp.async.cg.shared.global [%0], [%1], 16;" :: "r"(saddr), "l"(gaddr));
}
#define CP_COMMIT() asm volatile("cp.async.commit_group;" ::: "memory")
#define CP_WAIT(n) asm volatile("cp.async.wait_group %0;" :: "n"(n) : "memory")

__device__ __forceinline__ void ldmx4(uint32_t addr, uint32_t& r0, uint32_t& r1,
                                      uint32_t& r2, uint32_t& r3) {
    asm volatile("ldmatrix.sync.aligned.m8n8.x4.shared.b16 {%0,%1,%2,%3}, [%4];"
                 : "=r"(r0), "=r"(r1), "=r"(r2), "=r"(r3) : "r"(addr));
}
__device__ __forceinline__ void ldmx4t(uint32_t addr, uint32_t& r0, uint32_t& r1,
                                       uint32_t& r2, uint32_t& r3) {
    asm volatile("ldmatrix.sync.aligned.m8n8.x4.trans.shared.b16 {%0,%1,%2,%3}, [%4];"
                 : "=r"(r0), "=r"(r1), "=r"(r2), "=r"(r3) : "r"(addr));
}
__device__ __forceinline__ void ldmx2(uint32_t addr, uint32_t& r0, uint32_t& r1) {
    asm volatile("ldmatrix.sync.aligned.m8n8.x2.shared.b16 {%0,%1}, [%2];"
                 : "=r"(r0), "=r"(r1) : "r"(addr));
}
__device__ __forceinline__ void mma_bf16(float* c, uint32_t a0, uint32_t a1, uint32_t a2,
                                         uint32_t a3, uint32_t b0, uint32_t b1) {
    asm volatile(
        "mma.sync.aligned.m16n8k16.row.col.f32.bf16.bf16.f32 "
        "{%0,%1,%2,%3}, {%4,%5,%6,%7}, {%8,%9}, {%0,%1,%2,%3};"
        : "+f"(c[0]), "+f"(c[1]), "+f"(c[2]), "+f"(c[3])
        : "r"(a0), "r"(a1), "r"(a2), "r"(a3), "r"(b0), "r"(b1));
}

__device__ __forceinline__ unsigned short f2bf(float v) {
    __nv_bfloat16 b = __float2bfloat16(v);
    return *(unsigned short*)&b;
}
__device__ __forceinline__ float bf2f(unsigned short u) {
    __nv_bfloat16 b = *(__nv_bfloat16*)&u;
    return __bfloat162float(b);
}

// ---------------- Prep kernels ----------------------------------------------
__global__ __launch_bounds__(256) void xsplit(const float* __restrict__ X,
                                              unsigned short* __restrict__ hi,
                                              unsigned short* __restrict__ lo) {
    size_t i = ((size_t)blockIdx.x * 256 + threadIdx.x) * 4;
    float4 v = *(const float4*)(X + i);
    unsigned short h0 = f2bf(v.x), h1 = f2bf(v.y), h2 = f2bf(v.z), h3 = f2bf(v.w);
    unsigned short l0 = f2bf(v.x - bf2f(h0)), l1 = f2bf(v.y - bf2f(h1));
    unsigned short l2 = f2bf(v.z - bf2f(h2)), l3 = f2bf(v.w - bf2f(h3));
    *(uint2*)(hi + i) = make_uint2((uint32_t)h0 | ((uint32_t)h1 << 16),
                                   (uint32_t)h2 | ((uint32_t)h3 << 16));
    *(uint2*)(lo + i) = make_uint2((uint32_t)l0 | ((uint32_t)l1 << 16),
                                   (uint32_t)l2 | ((uint32_t)l3 << 16));
}

__global__ __launch_bounds__(256) void wsplit_t(const float* __restrict__ W,
                                                unsigned short* __restrict__ hi,
                                                unsigned short* __restrict__ lo) {
    __shared__ float s[32][33];
    int n0 = blockIdx.x * 32, k0 = blockIdx.y * 32;
    int tx = threadIdx.x & 31, ty = threadIdx.x >> 5;
#pragma unroll
    for (int d = 0; d < 4; d++) {
        int i = ty * 4 + d;
        s[i][tx] = W[(size_t)(k0 + i) * DM + n0 + tx];
    }
    __syncthreads();
#pragma unroll
    for (int d = 0; d < 4; d++) {
        int i = ty * 4 + d;
        float v = s[tx][i];
        unsigned short h = f2bf(v);
        unsigned short l = f2bf(v - bf2f(h));
        hi[(size_t)(n0 + i) * DM + k0 + tx] = h;
        lo[(size_t)(n0 + i) * DM + k0 + tx] = l;
    }
}

// ---------------- HMMA GEMM v2: cp.async 2-stage pipeline, SW128 swizzle -----
// C = A @ Bt^T, 3-term bf16 split. CTA 128x128, BK=64, 8 warps (2M x 4N).
// smem per stage: Ah/Al/Bh/Bl, each 128 rows x 128B SW128-swizzled = 16KB.
#define STG 65536
#define OF_AH 0
#define OF_AL 16384
#define OF_BH 32768
#define OF_BL 49152
#define MM_SMEM (2 * STG)

__global__ __launch_bounds__(256) void mm_hmma(const unsigned short* __restrict__ Ahi,
                                               const unsigned short* __restrict__ Alo,
                                               const unsigned short* __restrict__ Bhi,
                                               const unsigned short* __restrict__ Blo,
                                               float* __restrict__ Cf,
                                               unsigned short* __restrict__ Chi,
                                               unsigned short* __restrict__ Clo,
                                               int doRope) {
    extern __shared__ char smm[];
    const uint32_t smb = smem_u32(smm);
    const int tid = threadIdx.x;
    const int wid = tid >> 5, lid = tid & 31;
    const int wm = wid & 1, wn = wid >> 1;
    const int m0 = blockIdx.y * 128, n0 = blockIdx.x * 128;

    float acc[4][4][4] = {};

    // loader constants: thread t covers (row = id>>3, 16B chunk = id&7) x4
    const int lrow0 = tid >> 3, lch = tid & 7;
    const uint32_t lsw0 = (uint32_t)(lrow0 * 128 + ((lch * 16) ^ ((lrow0 & 7) << 4)));
    // each +32 rows: row*128 advances 4096; (row&7) unchanged
    // fragment constants
    const uint32_t xorv = (uint32_t)((lid & 7) << 4);
    const uint32_t aRow = (uint32_t)((wm * 64 + (lid & 15)) * 128);
    const uint32_t bRow = (uint32_t)((wn * 32 + (lid & 7)) * 128);
    const uint32_t aChBase = (uint32_t)((lid >> 4) << 4);
    const uint32_t bChBase = (uint32_t)(((lid >> 3) & 1) << 4);

#define LOAD_STAGE(k0c, stg) do {                                                  \
        uint32_t sb = smb + (stg)*STG;                                             \
        _Pragma("unroll")                                                          \
        for (int it = 0; it < 4; it++) {                                           \
            int row = lrow0 + it * 32;                                             \
            uint32_t so = lsw0 + it * 4096;                                        \
            size_t ga = (size_t)(m0 + row) * DM + (k0c) + lch * 8;                 \
            size_t gb = (size_t)(n0 + row) * DM + (k0c) + lch * 8;                 \
            cp16(sb + OF_AH + so, Ahi + ga);                                       \
            cp16(sb + OF_AL + so, Alo + ga);                                       \
            cp16(sb + OF_BH + so, Bhi + gb);                                       \
            cp16(sb + OF_BL + so, Blo + gb);                                       \
        }                                                                          \
        CP_COMMIT();                                                               \
    } while (0)

    LOAD_STAGE(0, 0);

    for (int c = 0; c < 16; c++) {
        if (c + 1 < 16) {
            LOAD_STAGE((c + 1) * 64, (c + 1) & 1);
            CP_WAIT(1);
        } else {
            CP_WAIT(0);
        }
        __syncthreads();

        const uint32_t st = smb + (c & 1) * STG;
        const uint32_t baseAh = st + OF_AH + aRow;
        const uint32_t baseAl = st + OF_AL + aRow;
        const uint32_t baseBh = st + OF_BH + bRow;
        const uint32_t baseBl = st + OF_BL + bRow;

#pragma unroll
        for (int ks = 0; ks < 4; ks++) {
            const uint32_t aCh = (uint32_t)(ks * 32 + aChBase) ^ xorv;
            const uint32_t bCh = (uint32_t)(ks * 32 + bChBase) ^ xorv;
            uint32_t bh[4][2], bl[4][2];
#pragma unroll
            for (int j = 0; j < 4; j++) {
                ldmx2(baseBh + j * 1024 + bCh, bh[j][0], bh[j][1]);
                ldmx2(baseBl + j * 1024 + bCh, bl[j][0], bl[j][1]);
            }
#pragma unroll
            for (int i = 0; i < 4; i++) {
                uint32_t ah0, ah1, ah2, ah3, al0, al1, al2, al3;
                ldmx4(baseAh + i * 2048 + aCh, ah0, ah1, ah2, ah3);
                ldmx4(baseAl + i * 2048 + aCh, al0, al1, al2, al3);
#pragma unroll
                for (int j = 0; j < 4; j++) {
                    mma_bf16(acc[i][j], ah0, ah1, ah2, ah3, bh[j][0], bh[j][1]);
                    mma_bf16(acc[i][j], ah0, ah1, ah2, ah3, bl[j][0], bl[j][1]);
                    mma_bf16(acc[i][j], al0, al1, al2, al3, bh[j][0], bh[j][1]);
                }
            }
        }
        __syncthreads();
    }

    const int quad = lid & 3, trow = lid >> 2;
#pragma unroll
    for (int i = 0; i < 4; i++) {
        int mA = m0 + wm * 64 + i * 16 + trow;
#pragma unroll
        for (int j = 0; j < 4; j++) {
            int n = n0 + wn * 32 + j * 8 + quad * 2;
            float e0 = acc[i][j][0], o0 = acc[i][j][1];
            float e1 = acc[i][j][2], o1 = acc[i][j][3];
            if (doRope) {
                int t = n & 63;
                float fr = (float)exp2(-(double)t * ROPE_LOG2C);
                float s, c;
                sincosf((float)mA * fr, &s, &c);
                float te = e0;
                e0 = te * c - o0 * s;
                o0 = te * s + o0 * c;
                sincosf((float)(mA + 8) * fr, &s, &c);
                te = e1;
                e1 = te * c - o1 * s;
                o1 = te * s + o1 * c;
            }
            size_t p0 = (size_t)mA * DM + n, p1 = (size_t)(mA + 8) * DM + n;
            if (Cf) {
                *(float2*)(Cf + p0) = make_float2(e0, o0);
                *(float2*)(Cf + p1) = make_float2(e1, o1);
            }
            if (Chi) {
                unsigned short he0 = f2bf(e0), ho0 = f2bf(o0);
                unsigned short he1 = f2bf(e1), ho1 = f2bf(o1);
                *(uint32_t*)(Chi + p0) = (uint32_t)he0 | ((uint32_t)ho0 << 16);
                *(uint32_t*)(Chi + p1) = (uint32_t)he1 | ((uint32_t)ho1 << 16);
                unsigned short le0 = f2bf(e0 - bf2f(he0)), lo0 = f2bf(o0 - bf2f(ho0));
                unsigned short le1 = f2bf(e1 - bf2f(he1)), lo1 = f2bf(o1 - bf2f(ho1));
                *(uint32_t*)(Clo + p0) = (uint32_t)le0 | ((uint32_t)lo0 << 16);
                *(uint32_t*)(Clo + p1) = (uint32_t)le1 | ((uint32_t)lo1 << 16);
            }
        }
    }
}

// ---------------- V chunk partials + suffix ---------------------------------
__global__ __launch_bounds__(256) void v_partial() {
    int j = blockIdx.x;
    int c = blockIdx.y * 256 + threadIdx.x;
    const float* base = g_V + (size_t)(j * 32) * DM + c;
    float s = 0.f;
#pragma unroll
    for (int r = 0; r < 32; r++) s += base[(size_t)r * DM];
    g_part[(size_t)j * DM + c] = s;
}
__global__ __launch_bounds__(256) void v_suffix2() {
    int j = blockIdx.x;
    int c = blockIdx.y * 256 + threadIdx.x;
    float s = 0.f;
    for (int i = j; i < 64; i++) s += g_part[(size_t)i * DM + c];
    g_Vsuf[(size_t)j * DM + c] = s;
}

// ---------------- Scores (HMMA) + head-axis softmax (unchanged) --------------
#define S_STRIDE 66
#define S_HEAD (32 * S_STRIDE)
__global__ __launch_bounds__(256) void attn_sc() {
    extern __shared__ char sms[];
    float* S = (float*)sms;
    unsigned short* Qh = (unsigned short*)(sms + 135168);
    unsigned short* Ql = Qh + 32 * 72;
    unsigned short* Kh = Ql + 32 * 72;
    unsigned short* Kl = Kh + 64 * 72;

    const int k0 = blockIdx.x * 64;
    const int q0 = blockIdx.y * 32;
    if (k0 >= (q0 & ~63) + 64) return;

    const int tid = threadIdx.x;
    const int wid = tid >> 5, lid = tid & 31;
    const int wm = wid & 1, wn = wid >> 1;
    const int trow = lid >> 2, quad = lid & 3;

    const uint32_t aOff = (uint32_t)((lid & 15) * 144 + (lid >> 4) * 16);
    const uint32_t bOff = (uint32_t)((lid & 7) * 144 + ((lid >> 3) & 1) * 16);
    const uint32_t baseQh = smem_u32(Qh) + wm * 16 * 144 + aOff;
    const uint32_t baseQl = smem_u32(Ql) + wm * 16 * 144 + aOff;
    const uint32_t baseKh = smem_u32(Kh) + wn * 16 * 144 + bOff;
    const uint32_t baseKl = smem_u32(Kl) + wn * 16 * 144 + bOff;

    const int lr = tid >> 3, lch = tid & 7;

    for (int h = 0; h < NH; h++) {
        __syncthreads();
        {
            size_t g = (size_t)(q0 + lr) * DM + h * HD + lch * 8;
            *(uint4*)((char*)Qh + lr * 144 + lch * 16) = *(const uint4*)(g_Qhi + g);
            *(uint4*)((char*)Ql + lr * 144 + lch * 16) = *(const uint4*)(g_Qlo + g);
        }
#pragma unroll
        for (int it = 0; it < 2; it++) {
            int ii = tid + it * 256;
            int rr = ii >> 3, ch = ii & 7;
            size_t g = (size_t)(k0 + rr) * DM + h * HD + ch * 8;
            *(uint4*)((char*)Kh + rr * 144 + ch * 16) = *(const uint4*)(g_Khi + g);
            *(uint4*)((char*)Kl + rr * 144 + ch * 16) = *(const uint4*)(g_Klo + g);
        }
        __syncthreads();

        float acc[2][4] = {};
#pragma unroll
        for (int ks = 0; ks < 4; ks++) {
            uint32_t qh0, qh1, qh2, qh3, ql0, ql1, ql2, ql3;
            ldmx4(baseQh + ks * 32, qh0, qh1, qh2, qh3);
            ldmx4(baseQl + ks * 32, ql0, ql1, ql2, ql3);
#pragma unroll
            for (int nf = 0; nf < 2; nf++) {
                uint32_t kh0, kh1, kl0, kl1;
                ldmx2(baseKh + nf * 1152 + ks * 32, kh0, kh1);
                ldmx2(baseKl + nf * 1152 + ks * 32, kl0, kl1);
                mma_bf16(acc[nf], qh0, qh1, qh2, qh3, kh0, kh1);
                mma_bf16(acc[nf], qh0, qh1, qh2, qh3, kl0, kl1);
                mma_bf16(acc[nf], ql0, ql1, ql2, ql3, kh0, kh1);
            }
        }
        float* Sh = S + h * S_HEAD;
#pragma unroll
        for (int nf = 0; nf < 2; nf++) {
            int row = wm * 16 + trow, col = wn * 16 + nf * 8 + quad * 2;
            Sh[row * S_STRIDE + col] = acc[nf][0] * 0.125f;
            Sh[row * S_STRIDE + col + 1] = acc[nf][1] * 0.125f;
            Sh[(row + 8) * S_STRIDE + col] = acc[nf][2] * 0.125f;
            Sh[(row + 8) * S_STRIDE + col + 1] = acc[nf][3] * 0.125f;
        }
    }
    __syncthreads();

#pragma unroll
    for (int it = 0; it < 8; it++) {
        int idx = tid + it * 256;
        int row = idx >> 6, col = idx & 63;
        int q = q0 + row, k = k0 + col;
        float* cell = S + row * S_STRIDE + col;
        if (k > q) {
#pragma unroll
            for (int h = 0; h < NH; h++) cell[h * S_HEAD] = 0.0625f;
        } else {
            float e[NH], mx = -1e30f;
#pragma unroll
            for (int h = 0; h < NH; h++) {
                e[h] = cell[h * S_HEAD];
                mx = fmaxf(mx, e[h]);
            }
            float sum = 0.f;
#pragma unroll
            for (int h = 0; h < NH; h++) {
                e[h] = __expf(e[h] - mx);
                sum += e[h];
            }
            float inv = 1.0f / sum;
#pragma unroll
            for (int h = 0; h < NH; h++) cell[h * S_HEAD] = e[h] * inv;
        }
    }
    __syncthreads();

    for (int it = 0; it < 128; it++) {
        int idx = tid + it * 256;
        int h = idx >> 11;
        int rem = idx & 2047;
        int row = rem >> 6, col = rem & 63;
        g_A[((size_t)h << 22) + (size_t)(q0 + row) * L + (k0 + col)] =
            S[h * S_HEAD + row * S_STRIDE + col];
    }
}

// ---------------- AV (HMMA, unchanged) ---------------------------------------
__global__ __launch_bounds__(256) void attn_av() {
    __shared__ __align__(16) unsigned short sAh[64 * 40];
    __shared__ __align__(16) unsigned short sAl[64 * 40];
    __shared__ __align__(16) unsigned short sVh[32 * 72];
    __shared__ __align__(16) unsigned short sVl[32 * 72];

    const int q0 = blockIdx.x * 64;
    const int h = blockIdx.y;
    const int tid = threadIdx.x;
    const int wid = tid >> 5, lid = tid & 31;
    const int wm = wid & 1, wn = wid >> 1;
    const int klim = q0 + 64;

    const float* Abase = g_A + ((size_t)h << 22);
    float acc[2][2][4] = {};

    const uint32_t aOff = (uint32_t)((lid & 15) * 80 + (lid >> 4) * 16);
    const uint32_t vOff =
        (uint32_t)((lid & 7) * 144 + ((lid >> 3) & 1) * 1152 + (lid >> 4) * 16);
    const uint32_t baseAh = smem_u32(sAh) + wm * 32 * 80 + aOff;
    const uint32_t baseAl = smem_u32(sAl) + wm * 32 * 80 + aOff;
    const uint32_t baseVh = smem_u32(sVh) + wn * 32 + vOff;
    const uint32_t baseVl = smem_u32(sVl) + wn * 32 + vOff;

    const int vr = tid >> 3, vch = tid & 7;

    for (int k0 = 0; k0 < klim; k0 += 32) {
        __syncthreads();
#pragma unroll
        for (int it = 0; it < 2; it++) {
            int ii = tid + it * 256;
            int r = ii >> 3, ch = ii & 7;
            float4 v = *(const float4*)(Abase + (size_t)(q0 + r) * L + k0 + ch * 4);
            unsigned short h0 = f2bf(v.x), h1 = f2bf(v.y), h2 = f2bf(v.z), h3 = f2bf(v.w);
            unsigned short l0 = f2bf(v.x - bf2f(h0)), l1 = f2bf(v.y - bf2f(h1));
            unsigned short l2 = f2bf(v.z - bf2f(h2)), l3 = f2bf(v.w - bf2f(h3));
            *(uint2*)((char*)sAh + r * 80 + ch * 8) =
                make_uint2((uint32_t)h0 | ((uint32_t)h1 << 16), (uint32_t)h2 | ((uint32_t)h3 << 16));
            *(uint2*)((char*)sAl + r * 80 + ch * 8) =
                make_uint2((uint32_t)l0 | ((uint32_t)l1 << 16), (uint32_t)l2 | ((uint32_t)l3 << 16));
        }
        {
            size_t g = (size_t)(k0 + vr) * DM + h * HD + vch * 8;
            *(uint4*)((char*)sVh + vr * 144 + vch * 16) = *(const uint4*)(g_Vhi + g);
            *(uint4*)((char*)sVl + vr * 144 + vch * 16) = *(const uint4*)(g_Vlo + g);
        }
        __syncthreads();

#pragma unroll
        for (int ks = 0; ks < 2; ks++) {
            uint32_t vh0, vh1, vh2, vh3, vl0, vl1, vl2, vl3;
            ldmx4t(baseVh + ks * 2304, vh0, vh1, vh2, vh3);
            ldmx4t(baseVl + ks * 2304, vl0, vl1, vl2, vl3);
#pragma unroll
            for (int mf = 0; mf < 2; mf++) {
                uint32_t ah0, ah1, ah2, ah3, al0, al1, al2, al3;
                ldmx4(baseAh + mf * 1280 + ks * 32, ah0, ah1, ah2, ah3);
                ldmx4(baseAl + mf * 1280 + ks * 32, al0, al1, al2, al3);
                mma_bf16(acc[mf][0], ah0, ah1, ah2, ah3, vh0, vh1);
                mma_bf16(acc[mf][0], ah0, ah1, ah2, ah3, vl0, vl1);
                mma_bf16(acc[mf][0], al0, al1, al2, al3, vh0, vh1);
                mma_bf16(acc[mf][1], ah0, ah1, ah2, ah3, vh2, vh3);
                mma_bf16(acc[mf][1], ah0, ah1, ah2, ah3, vl2, vl3);
                mma_bf16(acc[mf][1], al0, al1, al2, al3, vh2, vh3);
            }
        }
    }

    const int trow = lid >> 2, quad = lid & 3;
#pragma unroll
    for (int nf = 0; nf < 2; nf++) {
        int dc = wn * 16 + nf * 8 + quad * 2;
        float s0 = 0.f, s1 = 0.f;
        if (klim < L) {
            const float* sb = g_Vsuf + (size_t)(klim >> 5) * DM + h * HD;
            s0 = sb[dc] * 0.0625f;
            s1 = sb[dc + 1] * 0.0625f;
        }
#pragma unroll
        for (int mf = 0; mf < 2; mf++) {
            int m = q0 + wm * 32 + mf * 16 + trow;
            float y00 = acc[mf][nf][0] + s0, y01 = acc[mf][nf][1] + s1;
            float y10 = acc[mf][nf][2] + s0, y11 = acc[mf][nf][3] + s1;
            size_t p0 = (size_t)m * DM + h * HD + dc;
            size_t p1 = (size_t)(m + 8) * DM + h * HD + dc;
            unsigned short h00 = f2bf(y00), h01 = f2bf(y01);
            unsigned short h10 = f2bf(y10), h11 = f2bf(y11);
            *(uint32_t*)(g_Yhi + p0) = (uint32_t)h00 | ((uint32_t)h01 << 16);
            *(uint32_t*)(g_Yhi + p1) = (uint32_t)h10 | ((uint32_t)h11 << 16);
            unsigned short l00 = f2bf(y00 - bf2f(h00)), l01 = f2bf(y01 - bf2f(h01));
            unsigned short l10 = f2bf(y10 - bf2f(h10)), l11 = f2bf(y11 - bf2f(h11));
            *(uint32_t*)(g_Ylo + p0) = (uint32_t)l00 | ((uint32_t)l01 << 16);
            *(uint32_t*)(g_Ylo + p1) = (uint32_t)l10 | ((uint32_t)l11 << 16);
        }
    }
}

// ---------------------------------------------------------------------------
extern "C" void kernel_launch(void* const* d_in, const int* in_sizes, int n_in,
                              void* d_out, int out_size) {
    const float* X = (const float*)d_in[0];
    const float* Wq = (const float*)d_in[2];
    const float* Wk = (const float*)d_in[3];
    const float* Wv = (const float*)d_in[4];
    const float* Wo = (const float*)d_in[5];
    float* Out = (float*)d_out;

    float* Vp;
    unsigned short *Xhi, *Xlo, *Yhi, *Ylo, *Qhi, *Qlo, *Khi, *Klo, *Vhi, *Vlo, *Wth, *Wtl;
    cudaGetSymbolAddress((void**)&Vp, g_V);
    cudaGetSymbolAddress((void**)&Xhi, g_Xhi);
    cudaGetSymbolAddress((void**)&Xlo, g_Xlo);
    cudaGetSymbolAddress((void**)&Yhi, g_Yhi);
    cudaGetSymbolAddress((void**)&Ylo, g_Ylo);
    cudaGetSymbolAddress((void**)&Qhi, g_Qhi);
    cudaGetSymbolAddress((void**)&Qlo, g_Qlo);
    cudaGetSymbolAddress((void**)&Khi, g_Khi);
    cudaGetSymbolAddress((void**)&Klo, g_Klo);
    cudaGetSymbolAddress((void**)&Vhi, g_Vhi);
    cudaGetSymbolAddress((void**)&Vlo, g_Vlo);
    cudaGetSymbolAddress((void**)&Wth, g_Wthi);
    cudaGetSymbolAddress((void**)&Wtl, g_Wtlo);

    const int SMEM_SC = 135168 + 2 * 4608 + 2 * 9216;  // 162816 B
    cudaFuncSetAttribute(attn_sc, cudaFuncAttributeMaxDynamicSharedMemorySize, SMEM_SC);
    cudaFuncSetAttribute(mm_hmma, cudaFuncAttributeMaxDynamicSharedMemorySize, MM_SMEM);

    const size_t WSZ = (size_t)DM * DM;
    dim3 gW(DM / 32, DM / 32);
    wsplit_t<<<gW, 256>>>(Wq, Wth + 0 * WSZ, Wtl + 0 * WSZ);
    wsplit_t<<<gW, 256>>>(Wk, Wth + 1 * WSZ, Wtl + 1 * WSZ);
    wsplit_t<<<gW, 256>>>(Wv, Wth + 2 * WSZ, Wtl + 2 * WSZ);
    wsplit_t<<<gW, 256>>>(Wo, Wth + 3 * WSZ, Wtl + 3 * WSZ);

    xsplit<<<(L * DM) / 1024, 256>>>(X, Xhi, Xlo);

    dim3 gMM(DM / 128, L / 128);  // (8, 16)
    mm_hmma<<<gMM, 256, MM_SMEM>>>(Xhi, Xlo, Wth + 0 * WSZ, Wtl + 0 * WSZ, nullptr, Qhi, Qlo, 1);
    mm_hmma<<<gMM, 256, MM_SMEM>>>(Xhi, Xlo, Wth + 1 * WSZ, Wtl + 1 * WSZ, nullptr, Khi, Klo, 1);
    mm_hmma<<<gMM, 256, MM_SMEM>>>(Xhi, Xlo, Wth + 2 * WSZ, Wtl + 2 * WSZ, Vp, Vhi, Vlo, 0);

    v_partial<<<dim3(64, 4), 256>>>();
    v_suffix2<<<dim3(64, 4), 256>>>();

    attn_sc<<<dim3(L / 64, L / 32), 256, SMEM_SC>>>();
    attn_av<<<dim3(L / 64, NH), 256>>>();

    mm_hmma<<<gMM, 256, MM_SMEM>>>(Yhi, Ylo, Wth + 3 * WSZ, Wtl + 3 * WSZ, Out, nullptr, nullptr, 0);
}

// round 8
// speedup vs baseline: 3.7452x; 1.0052x over previous
#include <cuda_runtime.h>
#include <cuda_bf16.h>
#include <math.h>
#include <stdint.h>

#define L 2048
#define DM 1024
#define NH 16
#define HD 64

// ---------------- Scratch (device globals — no allocation allowed) ----------
__device__ __align__(16) float g_V[L * DM];
__device__ __align__(16) float g_part[64 * DM];
__device__ __align__(16) float g_Vsuf[64 * DM];
__device__ __align__(16) float g_A[(size_t)NH * L * L];  // fp32 head-softmaxed weights
__device__ __align__(16) unsigned short g_Xhi[L * DM];
__device__ __align__(16) unsigned short g_Xlo[L * DM];
__device__ __align__(16) unsigned short g_Yhi[L * DM];
__device__ __align__(16) unsigned short g_Ylo[L * DM];
__device__ __align__(16) unsigned short g_Qhi[L * DM];
__device__ __align__(16) unsigned short g_Qlo[L * DM];
__device__ __align__(16) unsigned short g_Khi[L * DM];
__device__ __align__(16) unsigned short g_Klo[L * DM];
__device__ __align__(16) unsigned short g_Vhi[L * DM];
__device__ __align__(16) unsigned short g_Vlo[L * DM];
__device__ __align__(16) unsigned short g_Wthi[4 * DM * DM];  // W^T [n][k]
__device__ __align__(16) unsigned short g_Wtlo[4 * DM * DM];

// -log2(500)/64
#define ROPE_LOG2C 0.14009037944784838

__device__ __forceinline__ uint32_t smem_u32(const void* p) {
    uint32_t a;
    asm("{ .reg .u64 t; cvta.to.shared.u64 t, %1; cvt.u32.u64 %0, t; }" : "=r"(a) : "l"(p));
    return a;
}
__device__ __forceinline__ void cp16(uint32_t saddr, const void* gaddr) {
    asm volatile("cp.async.cg.shared.global [%0], [%1], 16;" :: "r"(saddr), "l"(gaddr));
}
#define CP_COMMIT() asm volatile("cp.async.commit_group;" ::: "memory")
#define CP_WAIT(n) asm volatile("cp.async.wait_group %0;" :: "n"(n) : "memory")

__device__ __forceinline__ void ldmx4(uint32_t addr, uint32_t& r0, uint32_t& r1,
                                      uint32_t& r2, uint32_t& r3) {
    asm volatile("ldmatrix.sync.aligned.m8n8.x4.shared.b16 {%0,%1,%2,%3}, [%4];"
                 : "=r"(r0), "=r"(r1), "=r"(r2), "=r"(r3) : "r"(addr));
}
__device__ __forceinline__ void ldmx4t(uint32_t addr, uint32_t& r0, uint32_t& r1,
                                       uint32_t& r2, uint32_t& r3) {
    asm volatile("ldmatrix.sync.aligned.m8n8.x4.trans.shared.b16 {%0,%1,%2,%3}, [%4];"
                 : "=r"(r0), "=r"(r1), "=r"(r2), "=r"(r3) : "r"(addr));
}
__device__ __forceinline__ void ldmx2(uint32_t addr, uint32_t& r0, uint32_t& r1) {
    asm volatile("ldmatrix.sync.aligned.m8n8.x2.shared.b16 {%0,%1}, [%2];"
                 : "=r"(r0), "=r"(r1) : "r"(addr));
}
__device__ __forceinline__ void mma_bf16(float* c, uint32_t a0, uint32_t a1, uint32_t a2,
                                         uint32_t a3, uint32_t b0, uint32_t b1) {
    asm volatile(
        "mma.sync.aligned.m16n8k16.row.col.f32.bf16.bf16.f32 "
        "{%0,%1,%2,%3}, {%4,%5,%6,%7}, {%8,%9}, {%0,%1,%2,%3};"
        : "+f"(c[0]), "+f"(c[1]), "+f"(c[2]), "+f"(c[3])
        : "r"(a0), "r"(a1), "r"(a2), "r"(a3), "r"(b0), "r"(b1));
}

__device__ __forceinline__ unsigned short f2bf(float v) {
    __nv_bfloat16 b = __float2bfloat16(v);
    return *(unsigned short*)&b;
}
__device__ __forceinline__ float bf2f(unsigned short u) {
    __nv_bfloat16 b = *(__nv_bfloat16*)&u;
    return __bfloat162float(b);
}

// ---------------- Prep kernels ----------------------------------------------
__global__ __launch_bounds__(256) void xsplit(const float* __restrict__ X,
                                              unsigned short* __restrict__ hi,
                                              unsigned short* __restrict__ lo) {
    size_t i = ((size_t)blockIdx.x * 256 + threadIdx.x) * 4;
    float4 v = *(const float4*)(X + i);
    unsigned short h0 = f2bf(v.x), h1 = f2bf(v.y), h2 = f2bf(v.z), h3 = f2bf(v.w);
    unsigned short l0 = f2bf(v.x - bf2f(h0)), l1 = f2bf(v.y - bf2f(h1));
    unsigned short l2 = f2bf(v.z - bf2f(h2)), l3 = f2bf(v.w - bf2f(h3));
    *(uint2*)(hi + i) = make_uint2((uint32_t)h0 | ((uint32_t)h1 << 16),
                                   (uint32_t)h2 | ((uint32_t)h3 << 16));
    *(uint2*)(lo + i) = make_uint2((uint32_t)l0 | ((uint32_t)l1 << 16),
                                   (uint32_t)l2 | ((uint32_t)l3 << 16));
}

__global__ __launch_bounds__(256) void wsplit_t(const float* __restrict__ W,
                                                unsigned short* __restrict__ hi,
                                                unsigned short* __restrict__ lo) {
    __shared__ float s[32][33];
    int n0 = blockIdx.x * 32, k0 = blockIdx.y * 32;
    int tx = threadIdx.x & 31, ty = threadIdx.x >> 5;
#pragma unroll
    for (int d = 0; d < 4; d++) {
        int i = ty * 4 + d;
        s[i][tx] = W[(size_t)(k0 + i) * DM + n0 + tx];
    }
    __syncthreads();
#pragma unroll
    for (int d = 0; d < 4; d++) {
        int i = ty * 4 + d;
        float v = s[tx][i];
        unsigned short h = f2bf(v);
        unsigned short l = f2bf(v - bf2f(h));
        hi[(size_t)(n0 + i) * DM + k0 + tx] = h;
        lo[(size_t)(n0 + i) * DM + k0 + tx] = l;
    }
}

// ---------------- HMMA GEMM v3: 64x128 CTA tile, 2 CTAs/SM -------------------
// C = A @ Bt^T, 3-term bf16 split. BK=64, 8 warps (2M x 4N), warp tile 32x32.
// Stage smem: Ah/Al 8KB each + Bh/Bl 16KB each = 48KB; 2 stages = 96KB
// -> 2 CTAs/SM (16 warps/SM, 4/SMSP) for latency hiding.
#define OF_AH 0
#define OF_AL 8192
#define OF_BH 16384
#define OF_BL 32768
#define STG 49152
#define MM_SMEM (2 * STG)

__global__ __launch_bounds__(256, 2) void mm_hmma(const unsigned short* __restrict__ Ahi,
                                                  const unsigned short* __restrict__ Alo,
                                                  const unsigned short* __restrict__ Bhi,
                                                  const unsigned short* __restrict__ Blo,
                                                  float* __restrict__ Cf,
                                                  unsigned short* __restrict__ Chi,
                                                  unsigned short* __restrict__ Clo,
                                                  int doRope) {
    extern __shared__ char smm[];
    const uint32_t smb = smem_u32(smm);
    const int tid = threadIdx.x;
    const int wid = tid >> 5, lid = tid & 31;
    const int wm = wid & 1, wn = wid >> 1;
    const int m0 = blockIdx.y * 64, n0 = blockIdx.x * 128;

    float acc[2][4][4] = {};

    // loader: thread -> (row = tid>>3, 16B chunk = tid&7)
    const int lrow0 = tid >> 3, lch = tid & 7;
    const uint32_t lsw0 = (uint32_t)(lrow0 * 128 + ((lch * 16) ^ ((lrow0 & 7) << 4)));
    // fragment constants
    const uint32_t xorv = (uint32_t)((lid & 7) << 4);
    const uint32_t aRow = (uint32_t)((wm * 32 + (lid & 15)) * 128);
    const uint32_t bRow = (uint32_t)((wn * 32 + (lid & 7)) * 128);
    const uint32_t aChBase = (uint32_t)((lid >> 4) << 4);
    const uint32_t bChBase = (uint32_t)(((lid >> 3) & 1) << 4);

#define LOAD_STAGE(k0c, stg) do {                                                  \
        uint32_t sb = smb + (stg)*STG;                                             \
        _Pragma("unroll")                                                          \
        for (int it = 0; it < 2; it++) {                                           \
            int row = lrow0 + it * 32;                                             \
            uint32_t so = lsw0 + it * 4096;                                        \
            size_t ga = (size_t)(m0 + row) * DM + (k0c) + lch * 8;                 \
            cp16(sb + OF_AH + so, Ahi + ga);                                       \
            cp16(sb + OF_AL + so, Alo + ga);                                       \
        }                                                                          \
        _Pragma("unroll")                                                          \
        for (int it = 0; it < 4; it++) {                                           \
            int row = lrow0 + it * 32;                                             \
            uint32_t so = lsw0 + it * 4096;                                        \
            size_t gb = (size_t)(n0 + row) * DM + (k0c) + lch * 8;                 \
            cp16(sb + OF_BH + so, Bhi + gb);                                       \
            cp16(sb + OF_BL + so, Blo + gb);                                       \
        }                                                                          \
        CP_COMMIT();                                                               \
    } while (0)

    LOAD_STAGE(0, 0);

    for (int c = 0; c < 16; c++) {
        if (c + 1 < 16) {
            LOAD_STAGE((c + 1) * 64, (c + 1) & 1);
            CP_WAIT(1);
        } else {
            CP_WAIT(0);
        }
        __syncthreads();

        const uint32_t st = smb + (c & 1) * STG;
        const uint32_t baseAh = st + OF_AH + aRow;
        const uint32_t baseAl = st + OF_AL + aRow;
        const uint32_t baseBh = st + OF_BH + bRow;
        const uint32_t baseBl = st + OF_BL + bRow;

#pragma unroll
        for (int ks = 0; ks < 4; ks++) {
            const uint32_t aCh = (uint32_t)(ks * 32 + aChBase) ^ xorv;
            const uint32_t bCh = (uint32_t)(ks * 32 + bChBase) ^ xorv;
            uint32_t bh[4][2], bl[4][2];
#pragma unroll
            for (int j = 0; j < 4; j++) {
                ldmx2(baseBh + j * 1024 + bCh, bh[j][0], bh[j][1]);
                ldmx2(baseBl + j * 1024 + bCh, bl[j][0], bl[j][1]);
            }
#pragma unroll
            for (int i = 0; i < 2; i++) {
                uint32_t ah0, ah1, ah2, ah3, al0, al1, al2, al3;
                ldmx4(baseAh + i * 2048 + aCh, ah0, ah1, ah2, ah3);
                ldmx4(baseAl + i * 2048 + aCh, al0, al1, al2, al3);
#pragma unroll
                for (int j = 0; j < 4; j++) {
                    mma_bf16(acc[i][j], ah0, ah1, ah2, ah3, bh[j][0], bh[j][1]);
                    mma_bf16(acc[i][j], ah0, ah1, ah2, ah3, bl[j][0], bl[j][1]);
                    mma_bf16(acc[i][j], al0, al1, al2, al3, bh[j][0], bh[j][1]);
                }
            }
        }
        __syncthreads();
    }

    const int quad = lid & 3, trow = lid >> 2;
#pragma unroll
    for (int i = 0; i < 2; i++) {
        int mA = m0 + wm * 32 + i * 16 + trow;
#pragma unroll
        for (int j = 0; j < 4; j++) {
            int n = n0 + wn * 32 + j * 8 + quad * 2;
            float e0 = acc[i][j][0], o0 = acc[i][j][1];
            float e1 = acc[i][j][2], o1 = acc[i][j][3];
            if (doRope) {
                int t = n & 63;
                float fr = (float)exp2(-(double)t * ROPE_LOG2C);
                float s, c;
                sincosf((float)mA * fr, &s, &c);
                float te = e0;
                e0 = te * c - o0 * s;
                o0 = te * s + o0 * c;
                sincosf((float)(mA + 8) * fr, &s, &c);
                te = e1;
                e1 = te * c - o1 * s;
                o1 = te * s + o1 * c;
            }
            size_t p0 = (size_t)mA * DM + n, p1 = (size_t)(mA + 8) * DM + n;
            if (Cf) {
                *(float2*)(Cf + p0) = make_float2(e0, o0);
                *(float2*)(Cf + p1) = make_float2(e1, o1);
            }
            if (Chi) {
                unsigned short he0 = f2bf(e0), ho0 = f2bf(o0);
                unsigned short he1 = f2bf(e1), ho1 = f2bf(o1);
                *(uint32_t*)(Chi + p0) = (uint32_t)he0 | ((uint32_t)ho0 << 16);
                *(uint32_t*)(Chi + p1) = (uint32_t)he1 | ((uint32_t)ho1 << 16);
                unsigned short le0 = f2bf(e0 - bf2f(he0)), lo0 = f2bf(o0 - bf2f(ho0));
                unsigned short le1 = f2bf(e1 - bf2f(he1)), lo1 = f2bf(o1 - bf2f(ho1));
                *(uint32_t*)(Clo + p0) = (uint32_t)le0 | ((uint32_t)lo0 << 16);
                *(uint32_t*)(Clo + p1) = (uint32_t)le1 | ((uint32_t)lo1 << 16);
            }
        }
    }
}

// ---------------- V chunk partials + suffix ---------------------------------
__global__ __launch_bounds__(256) void v_partial() {
    int j = blockIdx.x;
    int c = blockIdx.y * 256 + threadIdx.x;
    const float* base = g_V + (size_t)(j * 32) * DM + c;
    float s = 0.f;
#pragma unroll
    for (int r = 0; r < 32; r++) s += base[(size_t)r * DM];
    g_part[(size_t)j * DM + c] = s;
}
__global__ __launch_bounds__(256) void v_suffix2() {
    int j = blockIdx.x;
    int c = blockIdx.y * 256 + threadIdx.x;
    float s = 0.f;
    for (int i = j; i < 64; i++) s += g_part[(size_t)i * DM + c];
    g_Vsuf[(size_t)j * DM + c] = s;
}

// ---------------- Scores (HMMA) + head-axis softmax --------------------------
#define S_STRIDE 66
#define S_HEAD (32 * S_STRIDE)
__global__ __launch_bounds__(256) void attn_sc() {
    extern __shared__ char sms[];
    float* S = (float*)sms;
    unsigned short* Qh = (unsigned short*)(sms + 135168);
    unsigned short* Ql = Qh + 32 * 72;
    unsigned short* Kh = Ql + 32 * 72;
    unsigned short* Kl = Kh + 64 * 72;

    const int k0 = blockIdx.x * 64;
    const int q0 = blockIdx.y * 32;
    if (k0 >= (q0 & ~63) + 64) return;

    const int tid = threadIdx.x;
    const int wid = tid >> 5, lid = tid & 31;
    const int wm = wid & 1, wn = wid >> 1;
    const int trow = lid >> 2, quad = lid & 3;

    const uint32_t aOff = (uint32_t)((lid & 15) * 144 + (lid >> 4) * 16);
    const uint32_t bOff = (uint32_t)((lid & 7) * 144 + ((lid >> 3) & 1) * 16);
    const uint32_t baseQh = smem_u32(Qh) + wm * 16 * 144 + aOff;
    const uint32_t baseQl = smem_u32(Ql) + wm * 16 * 144 + aOff;
    const uint32_t baseKh = smem_u32(Kh) + wn * 16 * 144 + bOff;
    const uint32_t baseKl = smem_u32(Kl) + wn * 16 * 144 + bOff;

    const int lr = tid >> 3, lch = tid & 7;

    for (int h = 0; h < NH; h++) {
        __syncthreads();
        {
            size_t g = (size_t)(q0 + lr) * DM + h * HD + lch * 8;
            *(uint4*)((char*)Qh + lr * 144 + lch * 16) = *(const uint4*)(g_Qhi + g);
            *(uint4*)((char*)Ql + lr * 144 + lch * 16) = *(const uint4*)(g_Qlo + g);
        }
#pragma unroll
        for (int it = 0; it < 2; it++) {
            int ii = tid + it * 256;
            int rr = ii >> 3, ch = ii & 7;
            size_t g = (size_t)(k0 + rr) * DM + h * HD + ch * 8;
            *(uint4*)((char*)Kh + rr * 144 + ch * 16) = *(const uint4*)(g_Khi + g);
            *(uint4*)((char*)Kl + rr * 144 + ch * 16) = *(const uint4*)(g_Klo + g);
        }
        __syncthreads();

        float acc[2][4] = {};
#pragma unroll
        for (int ks = 0; ks < 4; ks++) {
            uint32_t qh0, qh1, qh2, qh3, ql0, ql1, ql2, ql3;
            ldmx4(baseQh + ks * 32, qh0, qh1, qh2, qh3);
            ldmx4(baseQl + ks * 32, ql0, ql1, ql2, ql3);
#pragma unroll
            for (int nf = 0; nf < 2; nf++) {
                uint32_t kh0, kh1, kl0, kl1;
                ldmx2(baseKh + nf * 1152 + ks * 32, kh0, kh1);
                ldmx2(baseKl + nf * 1152 + ks * 32, kl0, kl1);
                mma_bf16(acc[nf], qh0, qh1, qh2, qh3, kh0, kh1);
                mma_bf16(acc[nf], qh0, qh1, qh2, qh3, kl0, kl1);
                mma_bf16(acc[nf], ql0, ql1, ql2, ql3, kh0, kh1);
            }
        }
        float* Sh = S + h * S_HEAD;
#pragma unroll
        for (int nf = 0; nf < 2; nf++) {
            int row = wm * 16 + trow, col = wn * 16 + nf * 8 + quad * 2;
            Sh[row * S_STRIDE + col] = acc[nf][0] * 0.125f;
            Sh[row * S_STRIDE + col + 1] = acc[nf][1] * 0.125f;
            Sh[(row + 8) * S_STRIDE + col] = acc[nf][2] * 0.125f;
            Sh[(row + 8) * S_STRIDE + col + 1] = acc[nf][3] * 0.125f;
        }
    }
    __syncthreads();

#pragma unroll
    for (int it = 0; it < 8; it++) {
        int idx = tid + it * 256;
        int row = idx >> 6, col = idx & 63;
        int q = q0 + row, k = k0 + col;
        float* cell = S + row * S_STRIDE + col;
        if (k > q) {
#pragma unroll
            for (int h = 0; h < NH; h++) cell[h * S_HEAD] = 0.0625f;
        } else {
            float e[NH], mx = -1e30f;
#pragma unroll
            for (int h = 0; h < NH; h++) {
                e[h] = cell[h * S_HEAD];
                mx = fmaxf(mx, e[h]);
            }
            float sum = 0.f;
#pragma unroll
            for (int h = 0; h < NH; h++) {
                e[h] = __expf(e[h] - mx);
                sum += e[h];
            }
            float inv = 1.0f / sum;
#pragma unroll
            for (int h = 0; h < NH; h++) cell[h * S_HEAD] = e[h] * inv;
        }
    }
    __syncthreads();

    for (int it = 0; it < 128; it++) {
        int idx = tid + it * 256;
        int h = idx >> 11;
        int rem = idx & 2047;
        int row = rem >> 6, col = rem & 63;
        g_A[((size_t)h << 22) + (size_t)(q0 + row) * L + (k0 + col)] =
            S[h * S_HEAD + row * S_STRIDE + col];
    }
}

// ---------------- AV (HMMA) ---------------------------------------------------
__global__ __launch_bounds__(256) void attn_av() {
    __shared__ __align__(16) unsigned short sAh[64 * 40];
    __shared__ __align__(16) unsigned short sAl[64 * 40];
    __shared__ __align__(16) unsigned short sVh[32 * 72];
    __shared__ __align__(16) unsigned short sVl[32 * 72];

    const int q0 = blockIdx.x * 64;
    const int h = blockIdx.y;
    const int tid = threadIdx.x;
    const int wid = tid >> 5, lid = tid & 31;
    const int wm = wid & 1, wn = wid >> 1;
    const int klim = q0 + 64;

    const float* Abase = g_A + ((size_t)h << 22);
    float acc[2][2][4] = {};

    const uint32_t aOff = (uint32_t)((lid & 15) * 80 + (lid >> 4) * 16);
    const uint32_t vOff =
        (uint32_t)((lid & 7) * 144 + ((lid >> 3) & 1) * 1152 + (lid >> 4) * 16);
    const uint32_t baseAh = smem_u32(sAh) + wm * 32 * 80 + aOff;
    const uint32_t baseAl = smem_u32(sAl) + wm * 32 * 80 + aOff;
    const uint32_t baseVh = smem_u32(sVh) + wn * 32 + vOff;
    const uint32_t baseVl = smem_u32(sVl) + wn * 32 + vOff;

    const int vr = tid >> 3, vch = tid & 7;

    for (int k0 = 0; k0 < klim; k0 += 32) {
        __syncthreads();
#pragma unroll
        for (int it = 0; it < 2; it++) {
            int ii = tid + it * 256;
            int r = ii >> 3, ch = ii & 7;
            float4 v = *(const float4*)(Abase + (size_t)(q0 + r) * L + k0 + ch * 4);
            unsigned short h0 = f2bf(v.x), h1 = f2bf(v.y), h2 = f2bf(v.z), h3 = f2bf(v.w);
            unsigned short l0 = f2bf(v.x - bf2f(h0)), l1 = f2bf(v.y - bf2f(h1));
            unsigned short l2 = f2bf(v.z - bf2f(h2)), l3 = f2bf(v.w - bf2f(h3));
            *(uint2*)((char*)sAh + r * 80 + ch * 8) =
                make_uint2((uint32_t)h0 | ((uint32_t)h1 << 16), (uint32_t)h2 | ((uint32_t)h3 << 16));
            *(uint2*)((char*)sAl + r * 80 + ch * 8) =
                make_uint2((uint32_t)l0 | ((uint32_t)l1 << 16), (uint32_t)l2 | ((uint32_t)l3 << 16));
        }
        {
            size_t g = (size_t)(k0 + vr) * DM + h * HD + vch * 8;
            *(uint4*)((char*)sVh + vr * 144 + vch * 16) = *(const uint4*)(g_Vhi + g);
            *(uint4*)((char*)sVl + vr * 144 + vch * 16) = *(const uint4*)(g_Vlo + g);
        }
        __syncthreads();

#pragma unroll
        for (int ks = 0; ks < 2; ks++) {
            uint32_t vh0, vh1, vh2, vh3, vl0, vl1, vl2, vl3;
            ldmx4t(baseVh + ks * 2304, vh0, vh1, vh2, vh3);
            ldmx4t(baseVl + ks * 2304, vl0, vl1, vl2, vl3);
#pragma unroll
            for (int mf = 0; mf < 2; mf++) {
                uint32_t ah0, ah1, ah2, ah3, al0, al1, al2, al3;
                ldmx4(baseAh + mf * 1280 + ks * 32, ah0, ah1, ah2, ah3);
                ldmx4(baseAl + mf * 1280 + ks * 32, al0, al1, al2, al3);
                mma_bf16(acc[mf][0], ah0, ah1, ah2, ah3, vh0, vh1);
                mma_bf16(acc[mf][0], ah0, ah1, ah2, ah3, vl0, vl1);
                mma_bf16(acc[mf][0], al0, al1, al2, al3, vh0, vh1);
                mma_bf16(acc[mf][1], ah0, ah1, ah2, ah3, vh2, vh3);
                mma_bf16(acc[mf][1], ah0, ah1, ah2, ah3, vl2, vl3);
                mma_bf16(acc[mf][1], al0, al1, al2, al3, vh2, vh3);
            }
        }
    }

    const int trow = lid >> 2, quad = lid & 3;
#pragma unroll
    for (int nf = 0; nf < 2; nf++) {
        int dc = wn * 16 + nf * 8 + quad * 2;
        float s0 = 0.f, s1 = 0.f;
        if (klim < L) {
            const float* sb = g_Vsuf + (size_t)(klim >> 5) * DM + h * HD;
            s0 = sb[dc] * 0.0625f;
            s1 = sb[dc + 1] * 0.0625f;
        }
#pragma unroll
        for (int mf = 0; mf < 2; mf++) {
            int m = q0 + wm * 32 + mf * 16 + trow;
            float y00 = acc[mf][nf][0] + s0, y01 = acc[mf][nf][1] + s1;
            float y10 = acc[mf][nf][2] + s0, y11 = acc[mf][nf][3] + s1;
            size_t p0 = (size_t)m * DM + h * HD + dc;
            size_t p1 = (size_t)(m + 8) * DM + h * HD + dc;
            unsigned short h00 = f2bf(y00), h01 = f2bf(y01);
            unsigned short h10 = f2bf(y10), h11 = f2bf(y11);
            *(uint32_t*)(g_Yhi + p0) = (uint32_t)h00 | ((uint32_t)h01 << 16);
            *(uint32_t*)(g_Yhi + p1) = (uint32_t)h10 | ((uint32_t)h11 << 16);
            unsigned short l00 = f2bf(y00 - bf2f(h00)), l01 = f2bf(y01 - bf2f(h01));
            unsigned short l10 = f2bf(y10 - bf2f(h10)), l11 = f2bf(y11 - bf2f(h11));
            *(uint32_t*)(g_Ylo + p0) = (uint32_t)l00 | ((uint32_t)l01 << 16);
            *(uint32_t*)(g_Ylo + p1) = (uint32_t)l10 | ((uint32_t)l11 << 16);
        }
    }
}

// ---------------------------------------------------------------------------
extern "C" void kernel_launch(void* const* d_in, const int* in_sizes, int n_in,
                              void* d_out, int out_size) {
    const float* X = (const float*)d_in[0];
    const float* Wq = (const float*)d_in[2];
    const float* Wk = (const float*)d_in[3];
    const float* Wv = (const float*)d_in[4];
    const float* Wo = (const float*)d_in[5];
    float* Out = (float*)d_out;

    float* Vp;
    unsigned short *Xhi, *Xlo, *Yhi, *Ylo, *Qhi, *Qlo, *Khi, *Klo, *Vhi, *Vlo, *Wth, *Wtl;
    cudaGetSymbolAddress((void**)&Vp, g_V);
    cudaGetSymbolAddress((void**)&Xhi, g_Xhi);
    cudaGetSymbolAddress((void**)&Xlo, g_Xlo);
    cudaGetSymbolAddress((void**)&Yhi, g_Yhi);
    cudaGetSymbolAddress((void**)&Ylo, g_Ylo);
    cudaGetSymbolAddress((void**)&Qhi, g_Qhi);
    cudaGetSymbolAddress((void**)&Qlo, g_Qlo);
    cudaGetSymbolAddress((void**)&Khi, g_Khi);
    cudaGetSymbolAddress((void**)&Klo, g_Klo);
    cudaGetSymbolAddress((void**)&Vhi, g_Vhi);
    cudaGetSymbolAddress((void**)&Vlo, g_Vlo);
    cudaGetSymbolAddress((void**)&Wth, g_Wthi);
    cudaGetSymbolAddress((void**)&Wtl, g_Wtlo);

    const int SMEM_SC = 135168 + 2 * 4608 + 2 * 9216;  // 162816 B
    cudaFuncSetAttribute(attn_sc, cudaFuncAttributeMaxDynamicSharedMemorySize, SMEM_SC);
    cudaFuncSetAttribute(mm_hmma, cudaFuncAttributeMaxDynamicSharedMemorySize, MM_SMEM);

    const size_t WSZ = (size_t)DM * DM;
    dim3 gW(DM / 32, DM / 32);
    wsplit_t<<<gW, 256>>>(Wq, Wth + 0 * WSZ, Wtl + 0 * WSZ);
    wsplit_t<<<gW, 256>>>(Wk, Wth + 1 * WSZ, Wtl + 1 * WSZ);
    wsplit_t<<<gW, 256>>>(Wv, Wth + 2 * WSZ, Wtl + 2 * WSZ);
    wsplit_t<<<gW, 256>>>(Wo, Wth + 3 * WSZ, Wtl + 3 * WSZ);

    xsplit<<<(L * DM) / 1024, 256>>>(X, Xhi, Xlo);

    dim3 gMM(DM / 128, L / 64);  // (8, 32) = 256 CTAs, 2/SM
    mm_hmma<<<gMM, 256, MM_SMEM>>>(Xhi, Xlo, Wth + 0 * WSZ, Wtl + 0 * WSZ, nullptr, Qhi, Qlo, 1);
    mm_hmma<<<gMM, 256, MM_SMEM>>>(Xhi, Xlo, Wth + 1 * WSZ, Wtl + 1 * WSZ, nullptr, Khi, Klo, 1);
    mm_hmma<<<gMM, 256, MM_SMEM>>>(Xhi, Xlo, Wth + 2 * WSZ, Wtl + 2 * WSZ, Vp, Vhi, Vlo, 0);

    v_partial<<<dim3(64, 4), 256>>>();
    v_suffix2<<<dim3(64, 4), 256>>>();

    attn_sc<<<dim3(L / 64, L / 32), 256, SMEM_SC>>>();
    attn_av<<<dim3(L / 64, NH), 256>>>();

    mm_hmma<<<gMM, 256, MM_SMEM>>>(Yhi, Ylo, Wth + 3 * WSZ, Wtl + 3 * WSZ, Out, nullptr, nullptr, 0);
}

// round 10
// speedup vs baseline: 4.8336x; 1.2906x over previous
#include <cuda_runtime.h>
#include <cuda_bf16.h>
#include <math.h>
#include <stdint.h>

#define L 2048
#define DM 1024
#define NH 16
#define HD 64

// ---------------- Scratch (device globals — no allocation allowed) ----------
__device__ __align__(16) float g_V[L * DM];
__device__ __align__(16) float g_part[64 * DM];
__device__ __align__(16) float g_Vsuf[64 * DM];
__device__ __align__(16) unsigned short g_Aah[(size_t)NH * L * L];  // A bf16 hi
__device__ __align__(16) unsigned short g_Aal[(size_t)NH * L * L];  // A bf16 lo
__device__ __align__(16) unsigned short g_Xhi[L * DM];
__device__ __align__(16) unsigned short g_Xlo[L * DM];
__device__ __align__(16) unsigned short g_Yhi[L * DM];
__device__ __align__(16) unsigned short g_Ylo[L * DM];
__device__ __align__(16) unsigned short g_Qhi[L * DM];
__device__ __align__(16) unsigned short g_Qlo[L * DM];
__device__ __align__(16) unsigned short g_Khi[L * DM];
__device__ __align__(16) unsigned short g_Klo[L * DM];
__device__ __align__(16) unsigned short g_Vhi[L * DM];
__device__ __align__(16) unsigned short g_Vlo[L * DM];
__device__ __align__(16) unsigned short g_Wthi[4 * DM * DM];  // W^T [n][k]
__device__ __align__(16) unsigned short g_Wtlo[4 * DM * DM];

// -log2(500)/64
#define ROPE_LOG2C 0.14009037944784838

__device__ __forceinline__ uint32_t smem_u32(const void* p) {
    uint32_t a;
    asm("{ .reg .u64 t; cvta.to.shared.u64 t, %1; cvt.u32.u64 %0, t; }" : "=r"(a) : "l"(p));
    return a;
}
__device__ __forceinline__ void cp16(uint32_t saddr, const void* gaddr) {
    asm volatile("cp.async.cg.shared.global [%0], [%1], 16;" :: "r"(saddr), "l"(gaddr));
}
#define CP_COMMIT() asm volatile("cp.async.commit_group;" ::: "memory")
#define CP_WAIT(n) asm volatile("cp.async.wait_group %0;" :: "n"(n) : "memory")

__device__ __forceinline__ void ldmx4(uint32_t addr, uint32_t& r0, uint32_t& r1,
                                      uint32_t& r2, uint32_t& r3) {
    asm volatile("ldmatrix.sync.aligned.m8n8.x4.shared.b16 {%0,%1,%2,%3}, [%4];"
                 : "=r"(r0), "=r"(r1), "=r"(r2), "=r"(r3) : "r"(addr));
}
__device__ __forceinline__ void ldmx4t(uint32_t addr, uint32_t& r0, uint32_t& r1,
                                       uint32_t& r2, uint32_t& r3) {
    asm volatile("ldmatrix.sync.aligned.m8n8.x4.trans.shared.b16 {%0,%1,%2,%3}, [%4];"
                 : "=r"(r0), "=r"(r1), "=r"(r2), "=r"(r3) : "r"(addr));
}
__device__ __forceinline__ void ldmx2(uint32_t addr, uint32_t& r0, uint32_t& r1) {
    asm volatile("ldmatrix.sync.aligned.m8n8.x2.shared.b16 {%0,%1}, [%2];"
                 : "=r"(r0), "=r"(r1) : "r"(addr));
}
__device__ __forceinline__ void mma_bf16(float* c, uint32_t a0, uint32_t a1, uint32_t a2,
                                         uint32_t a3, uint32_t b0, uint32_t b1) {
    asm volatile(
        "mma.sync.aligned.m16n8k16.row.col.f32.bf16.bf16.f32 "
        "{%0,%1,%2,%3}, {%4,%5,%6,%7}, {%8,%9}, {%0,%1,%2,%3};"
        : "+f"(c[0]), "+f"(c[1]), "+f"(c[2]), "+f"(c[3])
        : "r"(a0), "r"(a1), "r"(a2), "r"(a3), "r"(b0), "r"(b1));
}

__device__ __forceinline__ unsigned short f2bf(float v) {
    __nv_bfloat16 b = __float2bfloat16(v);
    return *(unsigned short*)&b;
}
__device__ __forceinline__ float bf2f(unsigned short u) {
    __nv_bfloat16 b = *(__nv_bfloat16*)&u;
    return __bfloat162float(b);
}

// ---------------- Prep kernels ----------------------------------------------
__global__ __launch_bounds__(256) void xsplit(const float* __restrict__ X,
                                              unsigned short* __restrict__ hi,
                                              unsigned short* __restrict__ lo) {
    size_t i = ((size_t)blockIdx.x * 256 + threadIdx.x) * 4;
    float4 v = *(const float4*)(X + i);
    unsigned short h0 = f2bf(v.x), h1 = f2bf(v.y), h2 = f2bf(v.z), h3 = f2bf(v.w);
    unsigned short l0 = f2bf(v.x - bf2f(h0)), l1 = f2bf(v.y - bf2f(h1));
    unsigned short l2 = f2bf(v.z - bf2f(h2)), l3 = f2bf(v.w - bf2f(h3));
    *(uint2*)(hi + i) = make_uint2((uint32_t)h0 | ((uint32_t)h1 << 16),
                                   (uint32_t)h2 | ((uint32_t)h3 << 16));
    *(uint2*)(lo + i) = make_uint2((uint32_t)l0 | ((uint32_t)l1 << 16),
                                   (uint32_t)l2 | ((uint32_t)l3 << 16));
}

__global__ __launch_bounds__(256) void wsplit_t(const float* __restrict__ W,
                                                unsigned short* __restrict__ hi,
                                                unsigned short* __restrict__ lo) {
    __shared__ float s[32][33];
    int n0 = blockIdx.x * 32, k0 = blockIdx.y * 32;
    int tx = threadIdx.x & 31, ty = threadIdx.x >> 5;
#pragma unroll
    for (int d = 0; d < 4; d++) {
        int i = ty * 4 + d;
        s[i][tx] = W[(size_t)(k0 + i) * DM + n0 + tx];
    }
    __syncthreads();
#pragma unroll
    for (int d = 0; d < 4; d++) {
        int i = ty * 4 + d;
        float v = s[tx][i];
        unsigned short h = f2bf(v);
        unsigned short l = f2bf(v - bf2f(h));
        hi[(size_t)(n0 + i) * DM + k0 + tx] = h;
        lo[(size_t)(n0 + i) * DM + k0 + tx] = l;
    }
}

// ---------------- HMMA GEMM (unchanged, known-good) --------------------------
#define OF_AH 0
#define OF_AL 8192
#define OF_BH 16384
#define OF_BL 32768
#define STG 49152
#define MM_SMEM (2 * STG)

__global__ __launch_bounds__(256, 2) void mm_hmma(const unsigned short* __restrict__ Ahi,
                                                  const unsigned short* __restrict__ Alo,
                                                  const unsigned short* __restrict__ Bhi,
                                                  const unsigned short* __restrict__ Blo,
                                                  float* __restrict__ Cf,
                                                  unsigned short* __restrict__ Chi,
                                                  unsigned short* __restrict__ Clo,
                                                  int doRope) {
    extern __shared__ char smm[];
    const uint32_t smb = smem_u32(smm);
    const int tid = threadIdx.x;
    const int wid = tid >> 5, lid = tid & 31;
    const int wm = wid & 1, wn = wid >> 1;
    const int m0 = blockIdx.y * 64, n0 = blockIdx.x * 128;

    float acc[2][4][4] = {};

    const int lrow0 = tid >> 3, lch = tid & 7;
    const uint32_t lsw0 = (uint32_t)(lrow0 * 128 + ((lch * 16) ^ ((lrow0 & 7) << 4)));
    const uint32_t xorv = (uint32_t)((lid & 7) << 4);
    const uint32_t aRow = (uint32_t)((wm * 32 + (lid & 15)) * 128);
    const uint32_t bRow = (uint32_t)((wn * 32 + (lid & 7)) * 128);
    const uint32_t aChBase = (uint32_t)((lid >> 4) << 4);
    const uint32_t bChBase = (uint32_t)(((lid >> 3) & 1) << 4);

#define LOAD_STAGE(k0c, stg) do {                                                  \
        uint32_t sb = smb + (stg)*STG;                                             \
        _Pragma("unroll")                                                          \
        for (int it = 0; it < 2; it++) {                                           \
            int row = lrow0 + it * 32;                                             \
            uint32_t so = lsw0 + it * 4096;                                        \
            size_t ga = (size_t)(m0 + row) * DM + (k0c) + lch * 8;                 \
            cp16(sb + OF_AH + so, Ahi + ga);                                       \
            cp16(sb + OF_AL + so, Alo + ga);                                       \
        }                                                                          \
        _Pragma("unroll")                                                          \
        for (int it = 0; it < 4; it++) {                                           \
            int row = lrow0 + it * 32;                                             \
            uint32_t so = lsw0 + it * 4096;                                        \
            size_t gb = (size_t)(n0 + row) * DM + (k0c) + lch * 8;                 \
            cp16(sb + OF_BH + so, Bhi + gb);                                       \
            cp16(sb + OF_BL + so, Blo + gb);                                       \
        }                                                                          \
        CP_COMMIT();                                                               \
    } while (0)

    LOAD_STAGE(0, 0);

    for (int c = 0; c < 16; c++) {
        if (c + 1 < 16) {
            LOAD_STAGE((c + 1) * 64, (c + 1) & 1);
            CP_WAIT(1);
        } else {
            CP_WAIT(0);
        }
        __syncthreads();

        const uint32_t st = smb + (c & 1) * STG;
        const uint32_t baseAh = st + OF_AH + aRow;
        const uint32_t baseAl = st + OF_AL + aRow;
        const uint32_t baseBh = st + OF_BH + bRow;
        const uint32_t baseBl = st + OF_BL + bRow;

#pragma unroll
        for (int ks = 0; ks < 4; ks++) {
            const uint32_t aCh = (uint32_t)(ks * 32 + aChBase) ^ xorv;
            const uint32_t bCh = (uint32_t)(ks * 32 + bChBase) ^ xorv;
            uint32_t bh[4][2], bl[4][2];
#pragma unroll
            for (int j = 0; j < 4; j++) {
                ldmx2(baseBh + j * 1024 + bCh, bh[j][0], bh[j][1]);
                ldmx2(baseBl + j * 1024 + bCh, bl[j][0], bl[j][1]);
            }
#pragma unroll
            for (int i = 0; i < 2; i++) {
                uint32_t ah0, ah1, ah2, ah3, al0, al1, al2, al3;
                ldmx4(baseAh + i * 2048 + aCh, ah0, ah1, ah2, ah3);
                ldmx4(baseAl + i * 2048 + aCh, al0, al1, al2, al3);
#pragma unroll
                for (int j = 0; j < 4; j++) {
                    mma_bf16(acc[i][j], ah0, ah1, ah2, ah3, bh[j][0], bh[j][1]);
                    mma_bf16(acc[i][j], ah0, ah1, ah2, ah3, bl[j][0], bl[j][1]);
                    mma_bf16(acc[i][j], al0, al1, al2, al3, bh[j][0], bh[j][1]);
                }
            }
        }
        __syncthreads();
    }

    const int quad = lid & 3, trow = lid >> 2;
#pragma unroll
    for (int i = 0; i < 2; i++) {
        int mA = m0 + wm * 32 + i * 16 + trow;
#pragma unroll
        for (int j = 0; j < 4; j++) {
            int n = n0 + wn * 32 + j * 8 + quad * 2;
            float e0 = acc[i][j][0], o0 = acc[i][j][1];
            float e1 = acc[i][j][2], o1 = acc[i][j][3];
            if (doRope) {
                int t = n & 63;
                float fr = (float)exp2(-(double)t * ROPE_LOG2C);
                float s, c;
                sincosf((float)mA * fr, &s, &c);
                float te = e0;
                e0 = te * c - o0 * s;
                o0 = te * s + o0 * c;
                sincosf((float)(mA + 8) * fr, &s, &c);
                te = e1;
                e1 = te * c - o1 * s;
                o1 = te * s + o1 * c;
            }
            size_t p0 = (size_t)mA * DM + n, p1 = (size_t)(mA + 8) * DM + n;
            if (Cf) {
                *(float2*)(Cf + p0) = make_float2(e0, o0);
                *(float2*)(Cf + p1) = make_float2(e1, o1);
            }
            if (Chi) {
                unsigned short he0 = f2bf(e0), ho0 = f2bf(o0);
                unsigned short he1 = f2bf(e1), ho1 = f2bf(o1);
                *(uint32_t*)(Chi + p0) = (uint32_t)he0 | ((uint32_t)ho0 << 16);
                *(uint32_t*)(Chi + p1) = (uint32_t)he1 | ((uint32_t)ho1 << 16);
                unsigned short le0 = f2bf(e0 - bf2f(he0)), lo0 = f2bf(o0 - bf2f(ho0));
                unsigned short le1 = f2bf(e1 - bf2f(he1)), lo1 = f2bf(o1 - bf2f(ho1));
                *(uint32_t*)(Clo + p0) = (uint32_t)le0 | ((uint32_t)lo0 << 16);
                *(uint32_t*)(Clo + p1) = (uint32_t)le1 | ((uint32_t)lo1 << 16);
            }
        }
    }
}

// ---------------- V chunk partials + suffix ---------------------------------
__global__ __launch_bounds__(256) void v_partial() {
    int j = blockIdx.x;
    int c = blockIdx.y * 256 + threadIdx.x;
    const float* base = g_V + (size_t)(j * 32) * DM + c;
    float s = 0.f;
#pragma unroll
    for (int r = 0; r < 32; r++) s += base[(size_t)r * DM];
    g_part[(size_t)j * DM + c] = s;
}
__global__ __launch_bounds__(256) void v_suffix2() {
    int j = blockIdx.x;
    int c = blockIdx.y * 256 + threadIdx.x;
    float s = 0.f;
    for (int i = j; i < 64; i++) s += g_part[(size_t)i * DM + c];
    g_Vsuf[(size_t)j * DM + c] = s;
}

// ---------------- Scores: cp.async pipelined head loop -----------------------
// CTA 32q x 64k, 16 heads. A written as bf16 hi/lo pairs.
#define S_STRIDE 66
#define S_HEAD (32 * S_STRIDE)
#define SC_QH 0
#define SC_QL 4608
#define SC_KH 9216
#define SC_KL 18432
#define SC_STG 27648
#define SC_SBASE 135168
#define SMEM_SC (SC_SBASE + 2 * SC_STG)  // 190464

__global__ __launch_bounds__(256) void attn_sc() {
    extern __shared__ char sms[];
    float* S = (float*)sms;
    const uint32_t smb = smem_u32(sms);

    const int k0 = blockIdx.x * 64;
    const int q0 = blockIdx.y * 32;
    if (k0 >= (q0 & ~63) + 64) return;

    const int tid = threadIdx.x;
    const int wid = tid >> 5, lid = tid & 31;
    const int wm = wid & 1, wn = wid >> 1;
    const int trow = lid >> 2, quad = lid & 3;

    const uint32_t qOff = (uint32_t)(wm * 16 * 144 + (lid & 15) * 144 + (lid >> 4) * 16);
    const uint32_t kOff = (uint32_t)(wn * 16 * 144 + (lid & 7) * 144 + ((lid >> 3) & 1) * 16);

#define SC_ISSUE(hh, stg) do {                                                          \
        uint32_t sb = smb + SC_SBASE + (stg)*SC_STG;                                    \
        _Pragma("unroll")                                                               \
        for (int c2 = 0; c2 < 2; c2++) {                                                \
            int c = tid + c2 * 256;                                                     \
            int arr = c >> 8, r = (c & 255) >> 3, ch = c & 7;                           \
            const unsigned short* src = arr ? g_Qlo : g_Qhi;                            \
            cp16(sb + (arr ? SC_QL : SC_QH) + r * 144 + ch * 16,                        \
                 src + (size_t)(q0 + r) * DM + (hh)*HD + ch * 8);                       \
        }                                                                               \
        _Pragma("unroll")                                                               \
        for (int c2 = 0; c2 < 4; c2++) {                                                \
            int c = tid + c2 * 256;                                                     \
            int arr = c >> 9, r = (c & 511) >> 3, ch = c & 7;                           \
            const unsigned short* src = arr ? g_Klo : g_Khi;                            \
            cp16(sb + (arr ? SC_KL : SC_KH) + r * 144 + ch * 16,                        \
                 src + (size_t)(k0 + r) * DM + (hh)*HD + ch * 8);                       \
        }                                                                               \
        CP_COMMIT();                                                                    \
    } while (0)

    SC_ISSUE(0, 0);

    for (int h = 0; h < NH; h++) {
        if (h + 1 < NH) {
            SC_ISSUE(h + 1, (h + 1) & 1);
            CP_WAIT(1);
        } else {
            CP_WAIT(0);
        }
        __syncthreads();

        const uint32_t st = smb + SC_SBASE + (h & 1) * SC_STG;
        const uint32_t baseQh = st + SC_QH + qOff;
        const uint32_t baseQl = st + SC_QL + qOff;
        const uint32_t baseKh = st + SC_KH + kOff;
        const uint32_t baseKl = st + SC_KL + kOff;

        float acc[2][4] = {};
#pragma unroll
        for (int ks = 0; ks < 4; ks++) {
            uint32_t qh0, qh1, qh2, qh3, ql0, ql1, ql2, ql3;
            ldmx4(baseQh + ks * 32, qh0, qh1, qh2, qh3);
            ldmx4(baseQl + ks * 32, ql0, ql1, ql2, ql3);
#pragma unroll
            for (int nf = 0; nf < 2; nf++) {
                uint32_t kh0, kh1, kl0, kl1;
                ldmx2(baseKh + nf * 1152 + ks * 32, kh0, kh1);
                ldmx2(baseKl + nf * 1152 + ks * 32, kl0, kl1);
                mma_bf16(acc[nf], qh0, qh1, qh2, qh3, kh0, kh1);
                mma_bf16(acc[nf], qh0, qh1, qh2, qh3, kl0, kl1);
                mma_bf16(acc[nf], ql0, ql1, ql2, ql3, kh0, kh1);
            }
        }
        float* Sh = S + h * S_HEAD;
#pragma unroll
        for (int nf = 0; nf < 2; nf++) {
            int row = wm * 16 + trow, col = wn * 16 + nf * 8 + quad * 2;
            Sh[row * S_STRIDE + col] = acc[nf][0] * 0.125f;
            Sh[row * S_STRIDE + col + 1] = acc[nf][1] * 0.125f;
            Sh[(row + 8) * S_STRIDE + col] = acc[nf][2] * 0.125f;
            Sh[(row + 8) * S_STRIDE + col + 1] = acc[nf][3] * 0.125f;
        }
        __syncthreads();
    }

    // Head-axis softmax per (q,k) cell
#pragma unroll
    for (int it = 0; it < 8; it++) {
        int idx = tid + it * 256;
        int row = idx >> 6, col = idx & 63;
        int q = q0 + row, k = k0 + col;
        float* cell = S + row * S_STRIDE + col;
        if (k > q) {
#pragma unroll
            for (int h = 0; h < NH; h++) cell[h * S_HEAD] = 0.0625f;
        } else {
            float e[NH], mx = -1e30f;
#pragma unroll
            for (int h = 0; h < NH; h++) {
                e[h] = cell[h * S_HEAD];
                mx = fmaxf(mx, e[h]);
            }
            float sum = 0.f;
#pragma unroll
            for (int h = 0; h < NH; h++) {
                e[h] = __expf(e[h] - mx);
                sum += e[h];
            }
            float inv = 1.0f / sum;
#pragma unroll
            for (int h = 0; h < NH; h++) cell[h * S_HEAD] = e[h] * inv;
        }
    }
    __syncthreads();

    // Writeback A as bf16 hi/lo pairs
    for (int it = 0; it < 64; it++) {
        int idx = tid + it * 256;
        int h = idx >> 10;
        int rem = idx & 1023;
        int row = rem >> 5, colp = (rem & 31) * 2;
        const float* cell = S + h * S_HEAD + row * S_STRIDE + colp;
        float a0 = cell[0], a1 = cell[1];
        unsigned short h0 = f2bf(a0), h1 = f2bf(a1);
        unsigned short l0 = f2bf(a0 - bf2f(h0)), l1 = f2bf(a1 - bf2f(h1));
        size_t p = ((size_t)h << 22) + (size_t)(q0 + row) * L + k0 + colp;
        *(uint32_t*)(g_Aah + p) = (uint32_t)h0 | ((uint32_t)h1 << 16);
        *(uint32_t*)(g_Aal + p) = (uint32_t)l0 | ((uint32_t)l1 << 16);
    }
}

// ---------------- AV v3: cp.async pipeline, 128B-row SW128 layout -------------
// A tile: 64 rows x 128B (chunks 0-3 = hi k0..31, chunks 4-7 = lo k0..31).
// V tiles: hi/lo each 32 rows x 128B (64 bf16 d-values = exactly one row).
#define AV_A 0
#define AV_VH 8192
#define AV_VL 12288
#define AV_STG 16384
#define AV_SMEM (2 * AV_STG)  // 32768

__global__ __launch_bounds__(256) void attn_av() {
    extern __shared__ char sma[];
    const uint32_t smb = smem_u32(sma);

    const int q0 = blockIdx.x * 64;
    const int h = blockIdx.y;
    const int tid = threadIdx.x;
    const int wid = tid >> 5, lid = tid & 31;
    const int wm = wid & 1, wn = wid >> 1;
    const int klim = q0 + 64, nIter = klim >> 5;

    float acc[2][2][4] = {};

    const uint32_t xorv = (uint32_t)((lid & 7) << 4);
    // A fragment: row = wm*32 + mf*16 + (lid&15); chunk base (lid>>4)<<4
    const uint32_t aRow = (uint32_t)((wm * 32 + (lid & 15)) * 128);
    const uint32_t aChBase = (uint32_t)((lid >> 4) << 4);
    // V fragment (trans): row = (lid&7) + 8*((lid>>3)&1) + 16*ks; col = wn*32 + ((lid>>4)<<4)
    const uint32_t vRow = (uint32_t)(((lid & 7) + 8 * ((lid >> 3) & 1)) * 128);
    const uint32_t vCh = (uint32_t)(wn * 32 + ((lid >> 4) << 4)) ^ xorv;

#define AV_ISSUE(k0c, stg) do {                                                          \
        uint32_t sb = smb + (stg)*AV_STG;                                                \
        _Pragma("unroll")                                                                \
        for (int c2 = 0; c2 < 2; c2++) {  /* A: 64 rows x 8 chunks = 512 */              \
            int c = tid + c2 * 256;                                                      \
            int r = c >> 3, ch = c & 7;                                                  \
            const unsigned short* src =                                                  \
                (ch < 4) ? (g_Aah + ((size_t)h << 22) + (size_t)(q0 + r) * L + (k0c) + ch * 8) \
                         : (g_Aal + ((size_t)h << 22) + (size_t)(q0 + r) * L + (k0c) + (ch - 4) * 8); \
            cp16(sb + AV_A + r * 128 + ((ch * 16) ^ ((r & 7) << 4)), src);               \
        }                                                                                \
        _Pragma("unroll")                                                                \
        for (int c2 = 0; c2 < 2; c2++) {  /* V: 2 arrays x 32 rows x 8 chunks = 512 */   \
            int c = tid + c2 * 256;                                                      \
            int arr = c >> 8, r = (c & 255) >> 3, ch = c & 7;                            \
            const unsigned short* src = arr ? g_Vlo : g_Vhi;                             \
            cp16(sb + (arr ? AV_VL : AV_VH) + r * 128 + ((ch * 16) ^ ((r & 7) << 4)),    \
                 src + (size_t)((k0c) + r) * DM + h * HD + ch * 8);                      \
        }                                                                                \
        CP_COMMIT();                                                                     \
    } while (0)

    AV_ISSUE(0, 0);

    for (int it = 0; it < nIter; it++) {
        if (it + 1 < nIter) {
            AV_ISSUE((it + 1) * 32, (it + 1) & 1);
            CP_WAIT(1);
        } else {
            CP_WAIT(0);
        }
        __syncthreads();

        const uint32_t st = smb + (it & 1) * AV_STG;
        const uint32_t baseA = st + AV_A + aRow;
        const uint32_t baseVh = st + AV_VH + vRow + vCh;
        const uint32_t baseVl = st + AV_VL + vRow + vCh;

#pragma unroll
        for (int ks = 0; ks < 2; ks++) {
            const uint32_t aChHi = (uint32_t)(ks * 32 + aChBase) ^ xorv;
            const uint32_t aChLo = (uint32_t)(64 + ks * 32 + aChBase) ^ xorv;
            uint32_t vh0, vh1, vh2, vh3, vl0, vl1, vl2, vl3;
            ldmx4t(baseVh + ks * 2048, vh0, vh1, vh2, vh3);
            ldmx4t(baseVl + ks * 2048, vl0, vl1, vl2, vl3);
#pragma unroll
            for (int mf = 0; mf < 2; mf++) {
                uint32_t ah0, ah1, ah2, ah3, al0, al1, al2, al3;
                ldmx4(baseA + mf * 2048 + aChHi, ah0, ah1, ah2, ah3);
                ldmx4(baseA + mf * 2048 + aChLo, al0, al1, al2, al3);
                mma_bf16(acc[mf][0], ah0, ah1, ah2, ah3, vh0, vh1);
                mma_bf16(acc[mf][0], ah0, ah1, ah2, ah3, vl0, vl1);
                mma_bf16(acc[mf][0], al0, al1, al2, al3, vh0, vh1);
                mma_bf16(acc[mf][1], ah0, ah1, ah2, ah3, vh2, vh3);
                mma_bf16(acc[mf][1], ah0, ah1, ah2, ah3, vl2, vl3);
                mma_bf16(acc[mf][1], al0, al1, al2, al3, vh2, vh3);
            }
        }
        __syncthreads();
    }

    const int trow = lid >> 2, quad = lid & 3;
#pragma unroll
    for (int nf = 0; nf < 2; nf++) {
        int dc = wn * 16 + nf * 8 + quad * 2;
        float s0 = 0.f, s1 = 0.f;
        if (klim < L) {
            const float* sb = g_Vsuf + (size_t)(klim >> 5) * DM + h * HD;
            s0 = sb[dc] * 0.0625f;
            s1 = sb[dc + 1] * 0.0625f;
        }
#pragma unroll
        for (int mf = 0; mf < 2; mf++) {
            int m = q0 + wm * 32 + mf * 16 + trow;
            float y00 = acc[mf][nf][0] + s0, y01 = acc[mf][nf][1] + s1;
            float y10 = acc[mf][nf][2] + s0, y11 = acc[mf][nf][3] + s1;
            size_t p0 = (size_t)m * DM + h * HD + dc;
            size_t p1 = (size_t)(m + 8) * DM + h * HD + dc;
            unsigned short h00 = f2bf(y00), h01 = f2bf(y01);
            unsigned short h10 = f2bf(y10), h11 = f2bf(y11);
            *(uint32_t*)(g_Yhi + p0) = (uint32_t)h00 | ((uint32_t)h01 << 16);
            *(uint32_t*)(g_Yhi + p1) = (uint32_t)h10 | ((uint32_t)h11 << 16);
            unsigned short l00 = f2bf(y00 - bf2f(h00)), l01 = f2bf(y01 - bf2f(h01));
            unsigned short l10 = f2bf(y10 - bf2f(h10)), l11 = f2bf(y11 - bf2f(h11));
            *(uint32_t*)(g_Ylo + p0) = (uint32_t)l00 | ((uint32_t)l01 << 16);
            *(uint32_t*)(g_Ylo + p1) = (uint32_t)l10 | ((uint32_t)l11 << 16);
        }
    }
}

// ---------------------------------------------------------------------------
extern "C" void kernel_launch(void* const* d_in, const int* in_sizes, int n_in,
                              void* d_out, int out_size) {
    const float* X = (const float*)d_in[0];
    const float* Wq = (const float*)d_in[2];
    const float* Wk = (const float*)d_in[3];
    const float* Wv = (const float*)d_in[4];
    const float* Wo = (const float*)d_in[5];
    float* Out = (float*)d_out;

    float* Vp;
    unsigned short *Xhi, *Xlo, *Yhi, *Ylo, *Qhi, *Qlo, *Khi, *Klo, *Vhi, *Vlo, *Wth, *Wtl;
    cudaGetSymbolAddress((void**)&Vp, g_V);
    cudaGetSymbolAddress((void**)&Xhi, g_Xhi);
    cudaGetSymbolAddress((void**)&Xlo, g_Xlo);
    cudaGetSymbolAddress((void**)&Yhi, g_Yhi);
    cudaGetSymbolAddress((void**)&Ylo, g_Ylo);
    cudaGetSymbolAddress((void**)&Qhi, g_Qhi);
    cudaGetSymbolAddress((void**)&Qlo, g_Qlo);
    cudaGetSymbolAddress((void**)&Khi, g_Khi);
    cudaGetSymbolAddress((void**)&Klo, g_Klo);
    cudaGetSymbolAddress((void**)&Vhi, g_Vhi);
    cudaGetSymbolAddress((void**)&Vlo, g_Vlo);
    cudaGetSymbolAddress((void**)&Wth, g_Wthi);
    cudaGetSymbolAddress((void**)&Wtl, g_Wtlo);

    cudaFuncSetAttribute(attn_sc, cudaFuncAttributeMaxDynamicSharedMemorySize, SMEM_SC);
    cudaFuncSetAttribute(mm_hmma, cudaFuncAttributeMaxDynamicSharedMemorySize, MM_SMEM);

    const size_t WSZ = (size_t)DM * DM;
    dim3 gW(DM / 32, DM / 32);
    wsplit_t<<<gW, 256>>>(Wq, Wth + 0 * WSZ, Wtl + 0 * WSZ);
    wsplit_t<<<gW, 256>>>(Wk, Wth + 1 * WSZ, Wtl + 1 * WSZ);
    wsplit_t<<<gW, 256>>>(Wv, Wth + 2 * WSZ, Wtl + 2 * WSZ);
    wsplit_t<<<gW, 256>>>(Wo, Wth + 3 * WSZ, Wtl + 3 * WSZ);

    xsplit<<<(L * DM) / 1024, 256>>>(X, Xhi, Xlo);

    dim3 gMM(DM / 128, L / 64);  // (8, 32)
    mm_hmma<<<gMM, 256, MM_SMEM>>>(Xhi, Xlo, Wth + 0 * WSZ, Wtl + 0 * WSZ, nullptr, Qhi, Qlo, 1);
    mm_hmma<<<gMM, 256, MM_SMEM>>>(Xhi, Xlo, Wth + 1 * WSZ, Wtl + 1 * WSZ, nullptr, Khi, Klo, 1);
    mm_hmma<<<gMM, 256, MM_SMEM>>>(Xhi, Xlo, Wth + 2 * WSZ, Wtl + 2 * WSZ, Vp, Vhi, Vlo, 0);

    v_partial<<<dim3(64, 4), 256>>>();
    v_suffix2<<<dim3(64, 4), 256>>>();

    attn_sc<<<dim3(L / 64, L / 32), 256, SMEM_SC>>>();
    attn_av<<<dim3(L / 64, NH), 256, AV_SMEM>>>();

    mm_hmma<<<gMM, 256, MM_SMEM>>>(Yhi, Ylo, Wth + 3 * WSZ, Wtl + 3 * WSZ, Out, nullptr, nullptr, 0);
}

// round 11
// speedup vs baseline: 5.0536x; 1.0455x over previous
#include <cuda_runtime.h>
#include <cuda_bf16.h>
#include <math.h>
#include <stdint.h>

#define L 2048
#define DM 1024
#define NH 16
#define HD 64

// ---------------- Scratch (device globals — no allocation allowed) ----------
__device__ __align__(16) float g_V[L * DM];
__device__ __align__(16) float g_part[64 * DM];
__device__ __align__(16) float g_Vsuf[64 * DM];
__device__ __align__(16) unsigned short g_Aah[(size_t)NH * L * L];  // A bf16 hi
__device__ __align__(16) unsigned short g_Aal[(size_t)NH * L * L];  // A bf16 lo
__device__ __align__(16) unsigned short g_Xhi[L * DM];
__device__ __align__(16) unsigned short g_Xlo[L * DM];
__device__ __align__(16) unsigned short g_Yhi[L * DM];
__device__ __align__(16) unsigned short g_Ylo[L * DM];
__device__ __align__(16) unsigned short g_Qhi[L * DM];
__device__ __align__(16) unsigned short g_Qlo[L * DM];
__device__ __align__(16) unsigned short g_Khi[L * DM];
__device__ __align__(16) unsigned short g_Klo[L * DM];
__device__ __align__(16) unsigned short g_Vhi[L * DM];
__device__ __align__(16) unsigned short g_Vlo[L * DM];
__device__ __align__(16) unsigned short g_Wthi[4 * DM * DM];  // W^T [n][k]
__device__ __align__(16) unsigned short g_Wtlo[4 * DM * DM];

// -log2(500)/64
#define ROPE_LOG2C 0.14009037944784838

__device__ __forceinline__ uint32_t smem_u32(const void* p) {
    uint32_t a;
    asm("{ .reg .u64 t; cvta.to.shared.u64 t, %1; cvt.u32.u64 %0, t; }" : "=r"(a) : "l"(p));
    return a;
}
__device__ __forceinline__ void cp16(uint32_t saddr, const void* gaddr) {
    asm volatile("cp.async.cg.shared.global [%0], [%1], 16;" :: "r"(saddr), "l"(gaddr));
}
#define CP_COMMIT() asm volatile("cp.async.commit_group;" ::: "memory")
#define CP_WAIT(n) asm volatile("cp.async.wait_group %0;" :: "n"(n) : "memory")

__device__ __forceinline__ void ldmx4(uint32_t addr, uint32_t& r0, uint32_t& r1,
                                      uint32_t& r2, uint32_t& r3) {
    asm volatile("ldmatrix.sync.aligned.m8n8.x4.shared.b16 {%0,%1,%2,%3}, [%4];"
                 : "=r"(r0), "=r"(r1), "=r"(r2), "=r"(r3) : "r"(addr));
}
__device__ __forceinline__ void ldmx4t(uint32_t addr, uint32_t& r0, uint32_t& r1,
                                       uint32_t& r2, uint32_t& r3) {
    asm volatile("ldmatrix.sync.aligned.m8n8.x4.trans.shared.b16 {%0,%1,%2,%3}, [%4];"
                 : "=r"(r0), "=r"(r1), "=r"(r2), "=r"(r3) : "r"(addr));
}
__device__ __forceinline__ void ldmx2(uint32_t addr, uint32_t& r0, uint32_t& r1) {
    asm volatile("ldmatrix.sync.aligned.m8n8.x2.shared.b16 {%0,%1}, [%2];"
                 : "=r"(r0), "=r"(r1) : "r"(addr));
}
__device__ __forceinline__ void mma_bf16(float* c, uint32_t a0, uint32_t a1, uint32_t a2,
                                         uint32_t a3, uint32_t b0, uint32_t b1) {
    asm volatile(
        "mma.sync.aligned.m16n8k16.row.col.f32.bf16.bf16.f32 "
        "{%0,%1,%2,%3}, {%4,%5,%6,%7}, {%8,%9}, {%0,%1,%2,%3};"
        : "+f"(c[0]), "+f"(c[1]), "+f"(c[2]), "+f"(c[3])
        : "r"(a0), "r"(a1), "r"(a2), "r"(a3), "r"(b0), "r"(b1));
}

__device__ __forceinline__ unsigned short f2bf(float v) {
    __nv_bfloat16 b = __float2bfloat16(v);
    return *(unsigned short*)&b;
}
__device__ __forceinline__ float bf2f(unsigned short u) {
    __nv_bfloat16 b = *(__nv_bfloat16*)&u;
    return __bfloat162float(b);
}

// ---------------- Prep kernels ----------------------------------------------
__global__ __launch_bounds__(256) void xsplit(const float* __restrict__ X,
                                              unsigned short* __restrict__ hi,
                                              unsigned short* __restrict__ lo) {
    size_t i = ((size_t)blockIdx.x * 256 + threadIdx.x) * 4;
    float4 v = *(const float4*)(X + i);
    unsigned short h0 = f2bf(v.x), h1 = f2bf(v.y), h2 = f2bf(v.z), h3 = f2bf(v.w);
    unsigned short l0 = f2bf(v.x - bf2f(h0)), l1 = f2bf(v.y - bf2f(h1));
    unsigned short l2 = f2bf(v.z - bf2f(h2)), l3 = f2bf(v.w - bf2f(h3));
    *(uint2*)(hi + i) = make_uint2((uint32_t)h0 | ((uint32_t)h1 << 16),
                                   (uint32_t)h2 | ((uint32_t)h3 << 16));
    *(uint2*)(lo + i) = make_uint2((uint32_t)l0 | ((uint32_t)l1 << 16),
                                   (uint32_t)l2 | ((uint32_t)l3 << 16));
}

// Fused: all 4 weight transposes+splits in one launch (z selects W)
__global__ __launch_bounds__(256) void wsplit4(const float* __restrict__ W0,
                                               const float* __restrict__ W1,
                                               const float* __restrict__ W2,
                                               const float* __restrict__ W3) {
    __shared__ float s[32][33];
    const int z = blockIdx.z;
    const float* W = (z == 0) ? W0 : (z == 1) ? W1 : (z == 2) ? W2 : W3;
    unsigned short* hi = g_Wthi + (size_t)z * DM * DM;
    unsigned short* lo = g_Wtlo + (size_t)z * DM * DM;
    int n0 = blockIdx.x * 32, k0 = blockIdx.y * 32;
    int tx = threadIdx.x & 31, ty = threadIdx.x >> 5;
#pragma unroll
    for (int d = 0; d < 4; d++) {
        int i = ty * 4 + d;
        s[i][tx] = W[(size_t)(k0 + i) * DM + n0 + tx];
    }
    __syncthreads();
#pragma unroll
    for (int d = 0; d < 4; d++) {
        int i = ty * 4 + d;
        float v = s[tx][i];
        unsigned short h = f2bf(v);
        unsigned short l = f2bf(v - bf2f(h));
        hi[(size_t)(n0 + i) * DM + k0 + tx] = h;
        lo[(size_t)(n0 + i) * DM + k0 + tx] = l;
    }
}

// ---------------- HMMA GEMM body (shared by QKV-fused and Wo kernels) --------
#define OF_AH 0
#define OF_AL 8192
#define OF_BH 16384
#define OF_BL 32768
#define STG 49152
#define MM_SMEM (2 * STG)

__device__ __forceinline__ void mm_body(uint32_t smb, char* smm,
                                        const unsigned short* __restrict__ Ahi,
                                        const unsigned short* __restrict__ Alo,
                                        const unsigned short* __restrict__ Bhi,
                                        const unsigned short* __restrict__ Blo,
                                        float* __restrict__ Cf,
                                        unsigned short* __restrict__ Chi,
                                        unsigned short* __restrict__ Clo,
                                        int doRope, int m0, int n0) {
    const int tid = threadIdx.x;
    const int wid = tid >> 5, lid = tid & 31;
    const int wm = wid & 1, wn = wid >> 1;

    float acc[2][4][4] = {};

    const int lrow0 = tid >> 3, lch = tid & 7;
    const uint32_t lsw0 = (uint32_t)(lrow0 * 128 + ((lch * 16) ^ ((lrow0 & 7) << 4)));
    const uint32_t xorv = (uint32_t)((lid & 7) << 4);
    const uint32_t aRow = (uint32_t)((wm * 32 + (lid & 15)) * 128);
    const uint32_t bRow = (uint32_t)((wn * 32 + (lid & 7)) * 128);
    const uint32_t aChBase = (uint32_t)((lid >> 4) << 4);
    const uint32_t bChBase = (uint32_t)(((lid >> 3) & 1) << 4);

#define LOAD_STAGE(k0c, stg) do {                                                  \
        uint32_t sb = smb + (stg)*STG;                                             \
        _Pragma("unroll")                                                          \
        for (int it = 0; it < 2; it++) {                                           \
            int row = lrow0 + it * 32;                                             \
            uint32_t so = lsw0 + it * 4096;                                        \
            size_t ga = (size_t)(m0 + row) * DM + (k0c) + lch * 8;                 \
            cp16(sb + OF_AH + so, Ahi + ga);                                       \
            cp16(sb + OF_AL + so, Alo + ga);                                       \
        }                                                                          \
        _Pragma("unroll")                                                          \
        for (int it = 0; it < 4; it++) {                                           \
            int row = lrow0 + it * 32;                                             \
            uint32_t so = lsw0 + it * 4096;                                        \
            size_t gb = (size_t)(n0 + row) * DM + (k0c) + lch * 8;                 \
            cp16(sb + OF_BH + so, Bhi + gb);                                       \
            cp16(sb + OF_BL + so, Blo + gb);                                       \
        }                                                                          \
        CP_COMMIT();                                                               \
    } while (0)

    LOAD_STAGE(0, 0);

    for (int c = 0; c < 16; c++) {
        if (c + 1 < 16) {
            LOAD_STAGE((c + 1) * 64, (c + 1) & 1);
            CP_WAIT(1);
        } else {
            CP_WAIT(0);
        }
        __syncthreads();

        const uint32_t st = smb + (c & 1) * STG;
        const uint32_t baseAh = st + OF_AH + aRow;
        const uint32_t baseAl = st + OF_AL + aRow;
        const uint32_t baseBh = st + OF_BH + bRow;
        const uint32_t baseBl = st + OF_BL + bRow;

#pragma unroll
        for (int ks = 0; ks < 4; ks++) {
            const uint32_t aCh = (uint32_t)(ks * 32 + aChBase) ^ xorv;
            const uint32_t bCh = (uint32_t)(ks * 32 + bChBase) ^ xorv;
            uint32_t bh[4][2], bl[4][2];
#pragma unroll
            for (int j = 0; j < 4; j++) {
                ldmx2(baseBh + j * 1024 + bCh, bh[j][0], bh[j][1]);
                ldmx2(baseBl + j * 1024 + bCh, bl[j][0], bl[j][1]);
            }
#pragma unroll
            for (int i = 0; i < 2; i++) {
                uint32_t ah0, ah1, ah2, ah3, al0, al1, al2, al3;
                ldmx4(baseAh + i * 2048 + aCh, ah0, ah1, ah2, ah3);
                ldmx4(baseAl + i * 2048 + aCh, al0, al1, al2, al3);
#pragma unroll
                for (int j = 0; j < 4; j++) {
                    mma_bf16(acc[i][j], ah0, ah1, ah2, ah3, bh[j][0], bh[j][1]);
                    mma_bf16(acc[i][j], ah0, ah1, ah2, ah3, bl[j][0], bl[j][1]);
                    mma_bf16(acc[i][j], al0, al1, al2, al3, bh[j][0], bh[j][1]);
                }
            }
        }
        __syncthreads();
    }

    const int quad = lid & 3, trow = lid >> 2;
#pragma unroll
    for (int i = 0; i < 2; i++) {
        int mA = m0 + wm * 32 + i * 16 + trow;
#pragma unroll
        for (int j = 0; j < 4; j++) {
            int n = n0 + wn * 32 + j * 8 + quad * 2;
            float e0 = acc[i][j][0], o0 = acc[i][j][1];
            float e1 = acc[i][j][2], o1 = acc[i][j][3];
            if (doRope) {
                int t = n & 63;
                float fr = (float)exp2(-(double)t * ROPE_LOG2C);
                float s, c;
                sincosf((float)mA * fr, &s, &c);
                float te = e0;
                e0 = te * c - o0 * s;
                o0 = te * s + o0 * c;
                sincosf((float)(mA + 8) * fr, &s, &c);
                te = e1;
                e1 = te * c - o1 * s;
                o1 = te * s + o1 * c;
            }
            size_t p0 = (size_t)mA * DM + n, p1 = (size_t)(mA + 8) * DM + n;
            if (Cf) {
                *(float2*)(Cf + p0) = make_float2(e0, o0);
                *(float2*)(Cf + p1) = make_float2(e1, o1);
            }
            if (Chi) {
                unsigned short he0 = f2bf(e0), ho0 = f2bf(o0);
                unsigned short he1 = f2bf(e1), ho1 = f2bf(o1);
                *(uint32_t*)(Chi + p0) = (uint32_t)he0 | ((uint32_t)ho0 << 16);
                *(uint32_t*)(Chi + p1) = (uint32_t)he1 | ((uint32_t)ho1 << 16);
                unsigned short le0 = f2bf(e0 - bf2f(he0)), lo0 = f2bf(o0 - bf2f(ho0));
                unsigned short le1 = f2bf(e1 - bf2f(he1)), lo1 = f2bf(o1 - bf2f(ho1));
                *(uint32_t*)(Clo + p0) = (uint32_t)le0 | ((uint32_t)lo0 << 16);
                *(uint32_t*)(Clo + p1) = (uint32_t)le1 | ((uint32_t)lo1 << 16);
            }
        }
    }
}

// Fused QKV GEMM: z=0 -> Q (rope), z=1 -> K (rope), z=2 -> V (fp32 + hi/lo)
__global__ __launch_bounds__(256, 2) void mm_qkv() {
    extern __shared__ char smm[];
    const int z = blockIdx.z;
    const unsigned short* Bhi = g_Wthi + (size_t)z * DM * DM;
    const unsigned short* Blo = g_Wtlo + (size_t)z * DM * DM;
    unsigned short* Chi = (z == 0) ? g_Qhi : (z == 1) ? g_Khi : g_Vhi;
    unsigned short* Clo = (z == 0) ? g_Qlo : (z == 1) ? g_Klo : g_Vlo;
    float* Cf = (z == 2) ? g_V : nullptr;
    mm_body(smem_u32(smm), smm, g_Xhi, g_Xlo, Bhi, Blo, Cf, Chi, Clo,
            (z < 2) ? 1 : 0, blockIdx.y * 64, blockIdx.x * 128);
}

// Final GEMM: Out = Y @ Wo^T (fp32 out)
__global__ __launch_bounds__(256, 2) void mm_out(float* __restrict__ Out) {
    extern __shared__ char smm[];
    mm_body(smem_u32(smm), smm, g_Yhi, g_Ylo, g_Wthi + (size_t)3 * DM * DM,
            g_Wtlo + (size_t)3 * DM * DM, Out, nullptr, nullptr, 0,
            blockIdx.y * 64, blockIdx.x * 128);
}

// ---------------- V chunk partials + suffix ---------------------------------
__global__ __launch_bounds__(256) void v_partial() {
    int j = blockIdx.x;
    int c = blockIdx.y * 256 + threadIdx.x;
    const float* base = g_V + (size_t)(j * 32) * DM + c;
    float s = 0.f;
#pragma unroll
    for (int r = 0; r < 32; r++) s += base[(size_t)r * DM];
    g_part[(size_t)j * DM + c] = s;
}
__global__ __launch_bounds__(256) void v_suffix2() {
    int j = blockIdx.x;
    int c = blockIdx.y * 256 + threadIdx.x;
    float s = 0.f;
    for (int i = j; i < 64; i++) s += g_part[(size_t)i * DM + c];
    g_Vsuf[(size_t)j * DM + c] = s;
}

// ---------------- Scores: cp.async pipelined head loop -----------------------
#define S_STRIDE 66
#define S_HEAD (32 * S_STRIDE)
#define SC_QH 0
#define SC_QL 4608
#define SC_KH 9216
#define SC_KL 18432
#define SC_STG 27648
#define SC_SBASE 135168
#define SMEM_SC (SC_SBASE + 2 * SC_STG)  // 190464

__global__ __launch_bounds__(256) void attn_sc() {
    extern __shared__ char sms[];
    float* S = (float*)sms;
    const uint32_t smb = smem_u32(sms);

    const int k0 = blockIdx.x * 64;
    const int q0 = blockIdx.y * 32;
    if (k0 >= (q0 & ~63) + 64) return;

    const int tid = threadIdx.x;

    // Fast path: tile entirely masked (all k > q) -> A = 1/16 exactly.
    // bf16 split of 0.0625 is (0x3D80, 0) — bit-identical to the slow path.
    if (k0 >= q0 + 32) {
        for (int it = 0; it < 64; it++) {
            int idx = tid + it * 256;
            int h = idx >> 10;
            int rem = idx & 1023;
            int row = rem >> 5, colp = (rem & 31) * 2;
            size_t p = ((size_t)h << 22) + (size_t)(q0 + row) * L + k0 + colp;
            *(uint32_t*)(g_Aah + p) = 0x3D803D80u;
            *(uint32_t*)(g_Aal + p) = 0u;
        }
        return;
    }

    const int wid = tid >> 5, lid = tid & 31;
    const int wm = wid & 1, wn = wid >> 1;
    const int trow = lid >> 2, quad = lid & 3;

    const uint32_t qOff = (uint32_t)(wm * 16 * 144 + (lid & 15) * 144 + (lid >> 4) * 16);
    const uint32_t kOff = (uint32_t)(wn * 16 * 144 + (lid & 7) * 144 + ((lid >> 3) & 1) * 16);

#define SC_ISSUE(hh, stg) do {                                                          \
        uint32_t sb = smb + SC_SBASE + (stg)*SC_STG;                                    \
        _Pragma("unroll")                                                               \
        for (int c2 = 0; c2 < 2; c2++) {                                                \
            int c = tid + c2 * 256;                                                     \
            int arr = c >> 8, r = (c & 255) >> 3, ch = c & 7;                           \
            const unsigned short* src = arr ? g_Qlo : g_Qhi;                            \
            cp16(sb + (arr ? SC_QL : SC_QH) + r * 144 + ch * 16,                        \
                 src + (size_t)(q0 + r) * DM + (hh)*HD + ch * 8);                       \
        }                                                                               \
        _Pragma("unroll")                                                               \
        for (int c2 = 0; c2 < 4; c2++) {                                                \
            int c = tid + c2 * 256;                                                     \
            int arr = c >> 9, r = (c & 511) >> 3, ch = c & 7;                           \
            const unsigned short* src = arr ? g_Klo : g_Khi;                            \
            cp16(sb + (arr ? SC_KL : SC_KH) + r * 144 + ch * 16,                        \
                 src + (size_t)(k0 + r) * DM + (hh)*HD + ch * 8);                       \
        }                                                                               \
        CP_COMMIT();                                                                    \
    } while (0)

    SC_ISSUE(0, 0);

    for (int h = 0; h < NH; h++) {
        if (h + 1 < NH) {
            SC_ISSUE(h + 1, (h + 1) & 1);
            CP_WAIT(1);
        } else {
            CP_WAIT(0);
        }
        __syncthreads();

        const uint32_t st = smb + SC_SBASE + (h & 1) * SC_STG;
        const uint32_t baseQh = st + SC_QH + qOff;
        const uint32_t baseQl = st + SC_QL + qOff;
        const uint32_t baseKh = st + SC_KH + kOff;
        const uint32_t baseKl = st + SC_KL + kOff;

        float acc[2][4] = {};
#pragma unroll
        for (int ks = 0; ks < 4; ks++) {
            uint32_t qh0, qh1, qh2, qh3, ql0, ql1, ql2, ql3;
            ldmx4(baseQh + ks * 32, qh0, qh1, qh2, qh3);
            ldmx4(baseQl + ks * 32, ql0, ql1, ql2, ql3);
#pragma unroll
            for (int nf = 0; nf < 2; nf++) {
                uint32_t kh0, kh1, kl0, kl1;
                ldmx2(baseKh + nf * 1152 + ks * 32, kh0, kh1);
                ldmx2(baseKl + nf * 1152 + ks * 32, kl0, kl1);
                mma_bf16(acc[nf], qh0, qh1, qh2, qh3, kh0, kh1);
                mma_bf16(acc[nf], qh0, qh1, qh2, qh3, kl0, kl1);
                mma_bf16(acc[nf], ql0, ql1, ql2, ql3, kh0, kh1);
            }
        }
        float* Sh = S + h * S_HEAD;
#pragma unroll
        for (int nf = 0; nf < 2; nf++) {
            int row = wm * 16 + trow, col = wn * 16 + nf * 8 + quad * 2;
            Sh[row * S_STRIDE + col] = acc[nf][0] * 0.125f;
            Sh[row * S_STRIDE + col + 1] = acc[nf][1] * 0.125f;
            Sh[(row + 8) * S_STRIDE + col] = acc[nf][2] * 0.125f;
            Sh[(row + 8) * S_STRIDE + col + 1] = acc[nf][3] * 0.125f;
        }
        __syncthreads();
    }

    // Head-axis softmax per (q,k) cell
#pragma unroll
    for (int it = 0; it < 8; it++) {
        int idx = tid + it * 256;
        int row = idx >> 6, col = idx & 63;
        int q = q0 + row, k = k0 + col;
        float* cell = S + row * S_STRIDE + col;
        if (k > q) {
#pragma unroll
            for (int h = 0; h < NH; h++) cell[h * S_HEAD] = 0.0625f;
        } else {
            float e[NH], mx = -1e30f;
#pragma unroll
            for (int h = 0; h < NH; h++) {
                e[h] = cell[h * S_HEAD];
                mx = fmaxf(mx, e[h]);
            }
            float sum = 0.f;
#pragma unroll
            for (int h = 0; h < NH; h++) {
                e[h] = __expf(e[h] - mx);
                sum += e[h];
            }
            float inv = 1.0f / sum;
#pragma unroll
            for (int h = 0; h < NH; h++) cell[h * S_HEAD] = e[h] * inv;
        }
    }
    __syncthreads();

    // Writeback A as bf16 hi/lo pairs
    for (int it = 0; it < 64; it++) {
        int idx = tid + it * 256;
        int h = idx >> 10;
        int rem = idx & 1023;
        int row = rem >> 5, colp = (rem & 31) * 2;
        const float* cell = S + h * S_HEAD + row * S_STRIDE + colp;
        float a0 = cell[0], a1 = cell[1];
        unsigned short h0 = f2bf(a0), h1 = f2bf(a1);
        unsigned short l0 = f2bf(a0 - bf2f(h0)), l1 = f2bf(a1 - bf2f(h1));
        size_t p = ((size_t)h << 22) + (size_t)(q0 + row) * L + k0 + colp;
        *(uint32_t*)(g_Aah + p) = (uint32_t)h0 | ((uint32_t)h1 << 16);
        *(uint32_t*)(g_Aal + p) = (uint32_t)l0 | ((uint32_t)l1 << 16);
    }
}

// ---------------- AV: cp.async pipeline, 128B-row SW128 layout ----------------
#define AV_A 0
#define AV_VH 8192
#define AV_VL 12288
#define AV_STG 16384
#define AV_SMEM (2 * AV_STG)  // 32768

__global__ __launch_bounds__(256) void attn_av() {
    extern __shared__ char sma[];
    const uint32_t smb = smem_u32(sma);

    const int q0 = blockIdx.x * 64;
    const int h = blockIdx.y;
    const int tid = threadIdx.x;
    const int wid = tid >> 5, lid = tid & 31;
    const int wm = wid & 1, wn = wid >> 1;
    const int klim = q0 + 64, nIter = klim >> 5;

    float acc[2][2][4] = {};

    const uint32_t xorv = (uint32_t)((lid & 7) << 4);
    const uint32_t aRow = (uint32_t)((wm * 32 + (lid & 15)) * 128);
    const uint32_t aChBase = (uint32_t)((lid >> 4) << 4);
    const uint32_t vRow = (uint32_t)(((lid & 7) + 8 * ((lid >> 3) & 1)) * 128);
    const uint32_t vCh = (uint32_t)(wn * 32 + ((lid >> 4) << 4)) ^ xorv;

#define AV_ISSUE(k0c, stg) do {                                                          \
        uint32_t sb = smb + (stg)*AV_STG;                                                \
        _Pragma("unroll")                                                                \
        for (int c2 = 0; c2 < 2; c2++) {                                                 \
            int c = tid + c2 * 256;                                                      \
            int r = c >> 3, ch = c & 7;                                                  \
            const unsigned short* src =                                                  \
                (ch < 4) ? (g_Aah + ((size_t)h << 22) + (size_t)(q0 + r) * L + (k0c) + ch * 8) \
                         : (g_Aal + ((size_t)h << 22) + (size_t)(q0 + r) * L + (k0c) + (ch - 4) * 8); \
            cp16(sb + AV_A + r * 128 + ((ch * 16) ^ ((r & 7) << 4)), src);               \
        }                                                                                \
        _Pragma("unroll")                                                                \
        for (int c2 = 0; c2 < 2; c2++) {                                                 \
            int c = tid + c2 * 256;                                                      \
            int arr = c >> 8, r = (c & 255) >> 3, ch = c & 7;                            \
            const unsigned short* src = arr ? g_Vlo : g_Vhi;                             \
            cp16(sb + (arr ? AV_VL : AV_VH) + r * 128 + ((ch * 16) ^ ((r & 7) << 4)),    \
                 src + (size_t)((k0c) + r) * DM + h * HD + ch * 8);                      \
        }                                                                                \
        CP_COMMIT();                                                                     \
    } while (0)

    AV_ISSUE(0, 0);

    for (int it = 0; it < nIter; it++) {
        if (it + 1 < nIter) {
            AV_ISSUE((it + 1) * 32, (it + 1) & 1);
            CP_WAIT(1);
        } else {
            CP_WAIT(0);
        }
        __syncthreads();

        const uint32_t st = smb + (it & 1) * AV_STG;
        const uint32_t baseA = st + AV_A + aRow;
        const uint32_t baseVh = st + AV_VH + vRow + vCh;
        const uint32_t baseVl = st + AV_VL + vRow + vCh;

#pragma unroll
        for (int ks = 0; ks < 2; ks++) {
            const uint32_t aChHi = (uint32_t)(ks * 32 + aChBase) ^ xorv;
            const uint32_t aChLo = (uint32_t)(64 + ks * 32 + aChBase) ^ xorv;
            uint32_t vh0, vh1, vh2, vh3, vl0, vl1, vl2, vl3;
            ldmx4t(baseVh + ks * 2048, vh0, vh1, vh2, vh3);
            ldmx4t(baseVl + ks * 2048, vl0, vl1, vl2, vl3);
#pragma unroll
            for (int mf = 0; mf < 2; mf++) {
                uint32_t ah0, ah1, ah2, ah3, al0, al1, al2, al3;
                ldmx4(baseA + mf * 2048 + aChHi, ah0, ah1, ah2, ah3);
                ldmx4(baseA + mf * 2048 + aChLo, al0, al1, al2, al3);
                mma_bf16(acc[mf][0], ah0, ah1, ah2, ah3, vh0, vh1);
                mma_bf16(acc[mf][0], ah0, ah1, ah2, ah3, vl0, vl1);
                mma_bf16(acc[mf][0], al0, al1, al2, al3, vh0, vh1);
                mma_bf16(acc[mf][1], ah0, ah1, ah2, ah3, vh2, vh3);
                mma_bf16(acc[mf][1], ah0, ah1, ah2, ah3, vl2, vl3);
                mma_bf16(acc[mf][1], al0, al1, al2, al3, vh2, vh3);
            }
        }
        __syncthreads();
    }

    const int trow = lid >> 2, quad = lid & 3;
#pragma unroll
    for (int nf = 0; nf < 2; nf++) {
        int dc = wn * 16 + nf * 8 + quad * 2;
        float s0 = 0.f, s1 = 0.f;
        if (klim < L) {
            const float* sb = g_Vsuf + (size_t)(klim >> 5) * DM + h * HD;
            s0 = sb[dc] * 0.0625f;
            s1 = sb[dc + 1] * 0.0625f;
        }
#pragma unroll
        for (int mf = 0; mf < 2; mf++) {
            int m = q0 + wm * 32 + mf * 16 + trow;
            float y00 = acc[mf][nf][0] + s0, y01 = acc[mf][nf][1] + s1;
            float y10 = acc[mf][nf][2] + s0, y11 = acc[mf][nf][3] + s1;
            size_t p0 = (size_t)m * DM + h * HD + dc;
            size_t p1 = (size_t)(m + 8) * DM + h * HD + dc;
            unsigned short h00 = f2bf(y00), h01 = f2bf(y01);
            unsigned short h10 = f2bf(y10), h11 = f2bf(y11);
            *(uint32_t*)(g_Yhi + p0) = (uint32_t)h00 | ((uint32_t)h01 << 16);
            *(uint32_t*)(g_Yhi + p1) = (uint32_t)h10 | ((uint32_t)h11 << 16);
            unsigned short l00 = f2bf(y00 - bf2f(h00)), l01 = f2bf(y01 - bf2f(h01));
            unsigned short l10 = f2bf(y10 - bf2f(h10)), l11 = f2bf(y11 - bf2f(h11));
            *(uint32_t*)(g_Ylo + p0) = (uint32_t)l00 | ((uint32_t)l01 << 16);
            *(uint32_t*)(g_Ylo + p1) = (uint32_t)l10 | ((uint32_t)l11 << 16);
        }
    }
}

// ---------------------------------------------------------------------------
extern "C" void kernel_launch(void* const* d_in, const int* in_sizes, int n_in,
                              void* d_out, int out_size) {
    const float* X = (const float*)d_in[0];
    const float* Wq = (const float*)d_in[2];
    const float* Wk = (const float*)d_in[3];
    const float* Wv = (const float*)d_in[4];
    const float* Wo = (const float*)d_in[5];
    float* Out = (float*)d_out;

    unsigned short *Xhi, *Xlo;
    cudaGetSymbolAddress((void**)&Xhi, g_Xhi);
    cudaGetSymbolAddress((void**)&Xlo, g_Xlo);

    cudaFuncSetAttribute(attn_sc, cudaFuncAttributeMaxDynamicSharedMemorySize, SMEM_SC);
    cudaFuncSetAttribute(mm_qkv, cudaFuncAttributeMaxDynamicSharedMemorySize, MM_SMEM);
    cudaFuncSetAttribute(mm_out, cudaFuncAttributeMaxDynamicSharedMemorySize, MM_SMEM);

    wsplit4<<<dim3(DM / 32, DM / 32, 4), 256>>>(Wq, Wk, Wv, Wo);
    xsplit<<<(L * DM) / 1024, 256>>>(X, Xhi, Xlo);

    mm_qkv<<<dim3(DM / 128, L / 64, 3), 256, MM_SMEM>>>();

    v_partial<<<dim3(64, 4), 256>>>();
    v_suffix2<<<dim3(64, 4), 256>>>();

    attn_sc<<<dim3(L / 64, L / 32), 256, SMEM_SC>>>();
    attn_av<<<dim3(L / 64, NH), 256, AV_SMEM>>>();

    mm_out<<<dim3(DM / 128, L / 64), 256, MM_SMEM>>>(Out);
}